// round 13
// baseline (speedup 1.0000x reference)
#include <cuda_runtime.h>
#include <cuda_bf16.h>
#include <cstdint>

#define NTOK 8192
#define DIM  128
#define CIN  256
#define HWD  1024
#define LOG2E 1.4426950408889634f
#define NSPLIT 2
#define KVTILES 64
#define GATE_CHUNKS 512      // 512 chunks x 512 k-rows = 262144
#define GATE1 320            // chunks in fat1
#define GATE2 (GATE_CHUNKS - GATE1)

// ---------------- device workspaces (no allocation allowed) ----------------
__device__ __align__(256) __nv_bfloat16 g_Q[NTOK * DIM];
__device__ __align__(256) __nv_bfloat16 g_K[NTOK * DIM];
__device__ __align__(256) __nv_bfloat16 g_V[NTOK * DIM];
__device__ __align__(256) float g_Opart[NSPLIT * NTOK * DIM];
__device__ float g_m[NSPLIT * NTOK];
__device__ float g_l[NSPLIT * NTOK];
__device__ float g_logits[8 * HWD];
__device__ float g_sp[8 * HWD];

// ---------------- PTX helpers ----------------
__device__ __forceinline__ uint32_t smem_u32(const void* p) {
    return (uint32_t)__cvta_generic_to_shared(p);
}
__device__ __forceinline__ void ldsm_x4(uint32_t& r0, uint32_t& r1, uint32_t& r2, uint32_t& r3, uint32_t a) {
    asm volatile("ldmatrix.sync.aligned.m8n8.x4.shared.b16 {%0,%1,%2,%3},[%4];"
                 : "=r"(r0), "=r"(r1), "=r"(r2), "=r"(r3) : "r"(a));
}
__device__ __forceinline__ void ldsm_x4_t(uint32_t& r0, uint32_t& r1, uint32_t& r2, uint32_t& r3, uint32_t a) {
    asm volatile("ldmatrix.sync.aligned.m8n8.x4.trans.shared.b16 {%0,%1,%2,%3},[%4];"
                 : "=r"(r0), "=r"(r1), "=r"(r2), "=r"(r3) : "r"(a));
}
__device__ __forceinline__ void mma16816(float c[4], const uint32_t a[4], uint32_t b0, uint32_t b1) {
    asm volatile("mma.sync.aligned.m16n8k16.row.col.f32.bf16.bf16.f32 "
                 "{%0,%1,%2,%3},{%4,%5,%6,%7},{%8,%9},{%0,%1,%2,%3};"
                 : "+f"(c[0]), "+f"(c[1]), "+f"(c[2]), "+f"(c[3])
                 : "r"(a[0]), "r"(a[1]), "r"(a[2]), "r"(a[3]), "r"(b0), "r"(b1));
}
__device__ __forceinline__ float ex2f(float x) {
    float r; asm("ex2.approx.f32 %0,%1;" : "=f"(r) : "f"(x)); return r;
}
__device__ __forceinline__ uint32_t packbf(float lo, float hi) {
    uint32_t r; asm("cvt.rn.bf16x2.f32 %0,%1,%2;" : "=r"(r) : "f"(hi), "f"(lo)); return r;
}
// packed f32x2 FMA (sm_103a; ptxas never emits from C++)
__device__ __forceinline__ void ffma2(unsigned long long& acc, unsigned long long a, unsigned long long b) {
    asm("fma.rn.f32x2 %0, %1, %2, %0;" : "+l"(acc) : "l"(a), "l"(b));
}
__device__ __forceinline__ unsigned long long bcast2(float v) {
    unsigned long long r; asm("mov.b64 %0, {%1, %1};" : "=l"(r) : "f"(v)); return r;
}
__device__ __forceinline__ float2 unpack2(unsigned long long v) {
    float2 r; asm("mov.b64 {%0, %1}, %2;" : "=f"(r.x), "=f"(r.y) : "l"(v)); return r;
}

// ==================== gate body: one 512-row k-chunk of x@W_dense ====================
// 128 threads; thread owns cols [tid*4, tid*4+3] and [512+tid*4, 512+tid*4+3]
__device__ void gate_body(const float* __restrict__ x, const float* __restrict__ Wd,
                          int chunk, float* xs /* >= 4096 floats */) {
    const int tid = threadIdx.x;
    const int k0 = chunk * 512;
    for (int i = tid; i < 4096; i += 128) {
        int kl = i & 511, b = i >> 9;
        xs[kl * 8 + b] = x[(size_t)b * 262144 + k0 + kl];
    }
    __syncthreads();

    unsigned long long acc[8][4];
#pragma unroll
    for (int b = 0; b < 8; ++b)
#pragma unroll
        for (int c = 0; c < 4; ++c) acc[b][c] = 0ull;

    const int cA = tid * 4, cB = 512 + tid * 4;
#pragma unroll 2
    for (int kl = 0; kl < 512; ++kl) {
        const float* wr = Wd + (size_t)(k0 + kl) * 1024;
        longlong2 wa = __ldcs((const longlong2*)(wr + cA));
        longlong2 wb = __ldcs((const longlong2*)(wr + cB));
        unsigned long long w0 = (unsigned long long)wa.x, w1 = (unsigned long long)wa.y;
        unsigned long long w2 = (unsigned long long)wb.x, w3 = (unsigned long long)wb.y;
        float4 xa = *(const float4*)&xs[kl * 8];
        float4 xb = *(const float4*)&xs[kl * 8 + 4];
        unsigned long long xp;
        xp = bcast2(xa.x); ffma2(acc[0][0], w0, xp); ffma2(acc[0][1], w1, xp); ffma2(acc[0][2], w2, xp); ffma2(acc[0][3], w3, xp);
        xp = bcast2(xa.y); ffma2(acc[1][0], w0, xp); ffma2(acc[1][1], w1, xp); ffma2(acc[1][2], w2, xp); ffma2(acc[1][3], w3, xp);
        xp = bcast2(xa.z); ffma2(acc[2][0], w0, xp); ffma2(acc[2][1], w1, xp); ffma2(acc[2][2], w2, xp); ffma2(acc[2][3], w3, xp);
        xp = bcast2(xa.w); ffma2(acc[3][0], w0, xp); ffma2(acc[3][1], w1, xp); ffma2(acc[3][2], w2, xp); ffma2(acc[3][3], w3, xp);
        xp = bcast2(xb.x); ffma2(acc[4][0], w0, xp); ffma2(acc[4][1], w1, xp); ffma2(acc[4][2], w2, xp); ffma2(acc[4][3], w3, xp);
        xp = bcast2(xb.y); ffma2(acc[5][0], w0, xp); ffma2(acc[5][1], w1, xp); ffma2(acc[5][2], w2, xp); ffma2(acc[5][3], w3, xp);
        xp = bcast2(xb.z); ffma2(acc[6][0], w0, xp); ffma2(acc[6][1], w1, xp); ffma2(acc[6][2], w2, xp); ffma2(acc[6][3], w3, xp);
        xp = bcast2(xb.w); ffma2(acc[7][0], w0, xp); ffma2(acc[7][1], w1, xp); ffma2(acc[7][2], w2, xp); ffma2(acc[7][3], w3, xp);
    }
#pragma unroll
    for (int b = 0; b < 8; ++b) {
        float2 v0 = unpack2(acc[b][0]);
        float2 v1 = unpack2(acc[b][1]);
        float2 v2 = unpack2(acc[b][2]);
        float2 v3 = unpack2(acc[b][3]);
        float* p = g_logits + b * HWD;
        atomicAdd(p + cA + 0, v0.x); atomicAdd(p + cA + 1, v0.y);
        atomicAdd(p + cA + 2, v1.x); atomicAdd(p + cA + 3, v1.y);
        atomicAdd(p + cB + 0, v2.x); atomicAdd(p + cB + 1, v2.y);
        atomicAdd(p + cB + 2, v3.x); atomicAdd(p + cB + 3, v3.y);
    }
}

// ==================== projection body: 32 tokens x 128 cols, K=256 ====================
__device__ void proj_body(const float* __restrict__ x, const float* __restrict__ W,
                          const float* __restrict__ bias, __nv_bfloat16* dst,
                          int t0, float4* sx /* 2048 float4 */) {
    const int tid = threadIdx.x;
    const float4* xg = (const float4*)(x + (size_t)t0 * CIN);
    for (int i = tid; i < 2048; i += 128) sx[i] = xg[i];
    __syncthreads();
    float acc[32];
#pragma unroll
    for (int t = 0; t < 32; ++t) acc[t] = 0.f;
    const int j = tid;
    for (int k4 = 0; k4 < 64; ++k4) {
        float w0 = W[(k4 * 4 + 0) * DIM + j];
        float w1 = W[(k4 * 4 + 1) * DIM + j];
        float w2 = W[(k4 * 4 + 2) * DIM + j];
        float w3 = W[(k4 * 4 + 3) * DIM + j];
#pragma unroll
        for (int t = 0; t < 32; ++t) {
            float4 v = sx[t * 64 + k4];
            acc[t] = fmaf(v.x, w0, acc[t]);
            acc[t] = fmaf(v.y, w1, acc[t]);
            acc[t] = fmaf(v.z, w2, acc[t]);
            acc[t] = fmaf(v.w, w3, acc[t]);
        }
    }
    float bj = bias[j];
#pragma unroll
    for (int t = 0; t < 32; ++t)
        dst[(size_t)(t0 + t) * DIM + j] = __float2bfloat16(acc[t] + bj);
}

// ==================== fat1: gate chunks 0..319 (first) + 768 proj blocks ====================
__global__ void __launch_bounds__(128) fat1_kernel(
    const float* __restrict__ x,
    const float* __restrict__ Wt, const float* __restrict__ bt,
    const float* __restrict__ Wp, const float* __restrict__ bp,
    const float* __restrict__ Wa, const float* __restrict__ ba,
    const float* __restrict__ Wd) {
    __shared__ __align__(16) float smem[8192];   // 32 KB
    const int bx = blockIdx.x;
    if (bx < GATE1) {
        gate_body(x, Wd, bx, smem);
        return;
    }
    const int pbx = bx - GATE1;
    const int sel = pbx >> 8;            // 0..2
    const int t0 = (pbx & 255) * 32;
    const float* W    = (sel == 0) ? Wt : (sel == 1) ? Wp : Wa;
    const float* bias = (sel == 0) ? bt : (sel == 1) ? bp : ba;
    __nv_bfloat16* dst = (sel == 0) ? g_Q : (sel == 1) ? g_K : g_V;
    proj_body(x, W, bias, dst, t0, (float4*)smem);
}

// ==================== fat2: flash (256 blocks, first) + gate chunks 320..511 ====================
#define ROWP 136
#define TILEB (64 * ROWP)
#define FLASH_SMEM (5 * TILEB * 2)

__device__ __forceinline__ void load_tile(__nv_bfloat16* dst, const __nv_bfloat16* src, int tid) {
#pragma unroll
    for (int it = 0; it < 8; ++it) {
        int c = tid + it * 128;
        int row = c >> 4, cc = c & 15;
        uint32_t d = smem_u32(dst + row * ROWP + cc * 8);
        const void* s = src + row * DIM + cc * 8;
        asm volatile("cp.async.cg.shared.global [%0],[%1],16;" :: "r"(d), "l"(s) : "memory");
    }
}

__global__ void __launch_bounds__(128, 2) fat2_kernel(const float* __restrict__ x,
                                                      const float* __restrict__ Wd) {
    extern __shared__ __align__(16) __nv_bfloat16 sh[];
    if (blockIdx.x >= 256) {
        gate_body(x, Wd, GATE1 + (int)blockIdx.x - 256, (float*)sh);
        return;
    }
    __nv_bfloat16* sQ = sh;
    __nv_bfloat16* sK = sh + TILEB;
    __nv_bfloat16* sV = sh + 3 * TILEB;
    const int tid = threadIdx.x, lane = tid & 31, warp = tid >> 5;
    const int q0 = ((int)blockIdx.x >> 1) * 64;
    const int split = blockIdx.x & 1;
    const __nv_bfloat16* Kbase = g_K + (size_t)split * KVTILES * 64 * DIM;
    const __nv_bfloat16* Vbase = g_V + (size_t)split * KVTILES * 64 * DIM;

    load_tile(sQ, g_Q + (size_t)q0 * DIM, tid);
    asm volatile("cp.async.commit_group;" ::: "memory");
    load_tile(sK, Kbase, tid);
    load_tile(sV, Vbase, tid);
    asm volatile("cp.async.commit_group;" ::: "memory");
    asm volatile("cp.async.wait_group 1;" ::: "memory");
    __syncthreads();

    uint32_t qf[8][4];
    {
        int row = warp * 16 + (lane & 7) + ((lane & 8) ? 8 : 0);
        int cb = (lane & 16) ? 8 : 0;
#pragma unroll
        for (int kk = 0; kk < 8; ++kk)
            ldsm_x4(qf[kk][0], qf[kk][1], qf[kk][2], qf[kk][3],
                    smem_u32(sQ + row * ROWP + kk * 16 + cb));
    }

    float oacc[16][4];
#pragma unroll
    for (int n = 0; n < 16; ++n) { oacc[n][0] = oacc[n][1] = oacc[n][2] = oacc[n][3] = 0.f; }
    float m0 = -1e30f, m1 = -1e30f, l0 = 0.f, l1 = 0.f;

    const int krow = (lane & 7) + ((lane & 16) ? 8 : 0);
    const int kc8  = (lane & 8) ? 8 : 0;
    const int vrow = (lane & 7) + ((lane & 8) ? 8 : 0);
    const int vc8  = (lane & 16) ? 8 : 0;

    for (int t = 0; t < KVTILES; ++t) {
        const int buf = t & 1;
        if (t < KVTILES - 1) {
            load_tile(sK + (1 - buf) * TILEB, Kbase + (size_t)(t + 1) * 64 * DIM, tid);
            load_tile(sV + (1 - buf) * TILEB, Vbase + (size_t)(t + 1) * 64 * DIM, tid);
        }
        asm volatile("cp.async.commit_group;" ::: "memory");
        asm volatile("cp.async.wait_group 1;" ::: "memory");
        __syncthreads();
        const __nv_bfloat16* kb = sK + buf * TILEB;
        const __nv_bfloat16* vb = sV + buf * TILEB;

        float sacc[8][4];
#pragma unroll
        for (int n = 0; n < 8; ++n) { sacc[n][0] = sacc[n][1] = sacc[n][2] = sacc[n][3] = 0.f; }
#pragma unroll
        for (int kk = 0; kk < 8; ++kk) {
#pragma unroll
            for (int np = 0; np < 4; ++np) {
                uint32_t b0, b1, b2, b3;
                ldsm_x4(b0, b1, b2, b3, smem_u32(kb + (np * 16 + krow) * ROWP + kk * 16 + kc8));
                mma16816(sacc[2 * np],     qf[kk], b0, b1);
                mma16816(sacc[2 * np + 1], qf[kk], b2, b3);
            }
        }

        float mx0 = -1e30f, mx1 = -1e30f;
#pragma unroll
        for (int n = 0; n < 8; ++n) {
            mx0 = fmaxf(mx0, fmaxf(sacc[n][0], sacc[n][1]));
            mx1 = fmaxf(mx1, fmaxf(sacc[n][2], sacc[n][3]));
        }
        mx0 = fmaxf(mx0, __shfl_xor_sync(0xffffffffu, mx0, 1));
        mx0 = fmaxf(mx0, __shfl_xor_sync(0xffffffffu, mx0, 2));
        mx1 = fmaxf(mx1, __shfl_xor_sync(0xffffffffu, mx1, 1));
        mx1 = fmaxf(mx1, __shfl_xor_sync(0xffffffffu, mx1, 2));
        float mn0 = fmaxf(m0, mx0), mn1 = fmaxf(m1, mx1);
        float sc0 = ex2f((m0 - mn0) * LOG2E), sc1 = ex2f((m1 - mn1) * LOG2E);
        float rs0 = 0.f, rs1 = 0.f;
#pragma unroll
        for (int n = 0; n < 8; ++n) {
            sacc[n][0] = ex2f((sacc[n][0] - mn0) * LOG2E);
            sacc[n][1] = ex2f((sacc[n][1] - mn0) * LOG2E);
            sacc[n][2] = ex2f((sacc[n][2] - mn1) * LOG2E);
            sacc[n][3] = ex2f((sacc[n][3] - mn1) * LOG2E);
            rs0 += sacc[n][0] + sacc[n][1];
            rs1 += sacc[n][2] + sacc[n][3];
        }
        rs0 += __shfl_xor_sync(0xffffffffu, rs0, 1);
        rs0 += __shfl_xor_sync(0xffffffffu, rs0, 2);
        rs1 += __shfl_xor_sync(0xffffffffu, rs1, 1);
        rs1 += __shfl_xor_sync(0xffffffffu, rs1, 2);
        l0 = l0 * sc0 + rs0; l1 = l1 * sc1 + rs1;
        m0 = mn0; m1 = mn1;
#pragma unroll
        for (int n = 0; n < 16; ++n) {
            oacc[n][0] *= sc0; oacc[n][1] *= sc0;
            oacc[n][2] *= sc1; oacc[n][3] *= sc1;
        }

        uint32_t pf[4][4];
#pragma unroll
        for (int i = 0; i < 4; ++i) {
            pf[i][0] = packbf(sacc[2 * i][0],     sacc[2 * i][1]);
            pf[i][1] = packbf(sacc[2 * i][2],     sacc[2 * i][3]);
            pf[i][2] = packbf(sacc[2 * i + 1][0], sacc[2 * i + 1][1]);
            pf[i][3] = packbf(sacc[2 * i + 1][2], sacc[2 * i + 1][3]);
        }

#pragma unroll
        for (int i = 0; i < 4; ++i) {
#pragma unroll
            for (int np = 0; np < 8; ++np) {
                uint32_t b0, b1, b2, b3;
                ldsm_x4_t(b0, b1, b2, b3, smem_u32(vb + (i * 16 + vrow) * ROWP + np * 16 + vc8));
                mma16816(oacc[2 * np],     pf[i], b0, b1);
                mma16816(oacc[2 * np + 1], pf[i], b2, b3);
            }
        }
        __syncthreads();
    }

    float* Op = g_Opart + (size_t)split * NTOK * DIM;
    int row0 = q0 + warp * 16 + (lane >> 2);
    int c0 = 2 * (lane & 3);
#pragma unroll
    for (int n = 0; n < 16; ++n) {
        int c = n * 8 + c0;
        *(float2*)&Op[(size_t)row0 * DIM + c]       = make_float2(oacc[n][0], oacc[n][1]);
        *(float2*)&Op[(size_t)(row0 + 8) * DIM + c] = make_float2(oacc[n][2], oacc[n][3]);
    }
    if ((lane & 3) == 0) {
        g_m[split * NTOK + row0] = m0;     g_l[split * NTOK + row0] = l0;
        g_m[split * NTOK + row0 + 8] = m1; g_l[split * NTOK + row0 + 8] = l1;
    }
}

// ==================== small kernels ====================
__global__ void zero_logits_kernel() {
    g_logits[blockIdx.x * 1024 + threadIdx.x] = 0.f;
}

__global__ void gate_softmax(const float* __restrict__ bd) {
    __shared__ float red[32];
    __shared__ float bc;
    const int b = blockIdx.x, j = threadIdx.x;
    const int lane = j & 31, w = j >> 5;
    float v = g_logits[b * HWD + j] + bd[j];
    float m = v;
#pragma unroll
    for (int o = 16; o; o >>= 1) m = fmaxf(m, __shfl_xor_sync(0xffffffffu, m, o));
    if (lane == 0) red[w] = m;
    __syncthreads();
    if (j < 32) {
        float t = red[j];
#pragma unroll
        for (int o = 16; o; o >>= 1) t = fmaxf(t, __shfl_xor_sync(0xffffffffu, t, o));
        if (j == 0) bc = t;
    }
    __syncthreads();
    float e = expf(v - bc);
    float s = e;
#pragma unroll
    for (int o = 16; o; o >>= 1) s += __shfl_xor_sync(0xffffffffu, s, o);
    if (lane == 0) red[w] = s;
    __syncthreads();
    if (j < 32) {
        float t = red[j];
#pragma unroll
        for (int o = 16; o; o >>= 1) t += __shfl_xor_sync(0xffffffffu, t, o);
        if (j == 0) bc = t;
    }
    __syncthreads();
    g_sp[b * HWD + j] = e / bc;
}

// ==================== epilogue: combine splits, (O @ W_mask) * sp + x ====================
__global__ void epilogue_kernel(const float* __restrict__ x, const float* __restrict__ Wm,
                                float* __restrict__ out) {
    __shared__ float4 sO[32 * 32];
    __shared__ float ssp[32], sw0[32], sw1[32], sinv[32];
    const int tid = threadIdx.x;
    const int t0 = blockIdx.x * 32;
    if (tid < 32) {
        int r = t0 + tid;
        float m0 = g_m[r], m1 = g_m[NTOK + r];
        float l0 = g_l[r], l1 = g_l[NTOK + r];
        float mm = fmaxf(m0, m1);
        float w0 = ex2f((m0 - mm) * LOG2E), w1 = ex2f((m1 - mm) * LOG2E);
        sw0[tid] = w0; sw1[tid] = w1;
        sinv[tid] = 1.f / (l0 * w0 + l1 * w1);
        ssp[tid] = g_sp[r];
    }
    __syncthreads();
    const float4* o0 = (const float4*)(g_Opart + (size_t)t0 * DIM);
    const float4* o1 = (const float4*)(g_Opart + (size_t)NTOK * DIM + (size_t)t0 * DIM);
    for (int i = tid; i < 1024; i += 256) {
        int t = i >> 5;
        float w0 = sw0[t] * sinv[t], w1 = sw1[t] * sinv[t];
        float4 a = o0[i], b = o1[i];
        sO[i] = make_float4(a.x * w0 + b.x * w1, a.y * w0 + b.y * w1,
                            a.z * w0 + b.z * w1, a.w * w0 + b.w * w1);
    }
    __syncthreads();
    const int j = tid;
    float acc[32];
#pragma unroll
    for (int t = 0; t < 32; ++t) acc[t] = 0.f;
    for (int k4 = 0; k4 < 32; ++k4) {
        float w0 = Wm[(k4 * 4 + 0) * CIN + j];
        float w1 = Wm[(k4 * 4 + 1) * CIN + j];
        float w2 = Wm[(k4 * 4 + 2) * CIN + j];
        float w3 = Wm[(k4 * 4 + 3) * CIN + j];
#pragma unroll
        for (int t = 0; t < 32; ++t) {
            float4 v = sO[t * 32 + k4];
            acc[t] = fmaf(v.x, w0, acc[t]);
            acc[t] = fmaf(v.y, w1, acc[t]);
            acc[t] = fmaf(v.z, w2, acc[t]);
            acc[t] = fmaf(v.w, w3, acc[t]);
        }
    }
#pragma unroll
    for (int t = 0; t < 32; ++t)
        out[(size_t)(t0 + t) * CIN + j] = acc[t] * ssp[t] + x[(size_t)(t0 + t) * CIN + j];
}

// ==================== launcher ====================
extern "C" void kernel_launch(void* const* d_in, const int* in_sizes, int n_in,
                              void* d_out, int out_size) {
    const float* x  = (const float*)d_in[0];
    const float* Wt = (const float*)d_in[1];
    const float* bt = (const float*)d_in[2];
    const float* Wp = (const float*)d_in[3];
    const float* bp = (const float*)d_in[4];
    const float* Wa = (const float*)d_in[5];
    const float* ba = (const float*)d_in[6];
    const float* Wm = (const float*)d_in[7];
    const float* Wd = (const float*)d_in[8];
    const float* bd = (const float*)d_in[9];
    float* out = (float*)d_out;

    cudaFuncSetAttribute(fat2_kernel, cudaFuncAttributeMaxDynamicSharedMemorySize, FLASH_SMEM);

    zero_logits_kernel<<<8, 1024>>>();
    fat1_kernel<<<GATE1 + 768, 128>>>(x, Wt, bt, Wp, bp, Wa, ba, Wd);
    fat2_kernel<<<256 + GATE2, 128, FLASH_SMEM>>>(x, Wd);
    gate_softmax<<<8, 1024>>>(bd);
    epilogue_kernel<<<256, 256>>>(x, Wm, out);
}

// round 14
// speedup vs baseline: 1.2744x; 1.2744x over previous
#include <cuda_runtime.h>
#include <cuda_bf16.h>
#include <cstdint>

#define NTOK 8192
#define DIM  128
#define CIN  256
#define HWD  1024
#define LOG2E 1.4426950408889634f
#define NSPLIT 2
#define KVTILES 64
#define GATE_CHUNKS 512      // 512 chunks x 512 k-rows = 262144

// ---------------- device workspaces (no allocation allowed) ----------------
__device__ __align__(256) __nv_bfloat16 g_xb[NTOK * CIN];      // x in bf16
__device__ __align__(256) __nv_bfloat16 g_Wb[3 * DIM * CIN];   // W^T bf16: [sel][n][k]
__device__ __align__(256) __nv_bfloat16 g_Q[NTOK * DIM];
__device__ __align__(256) __nv_bfloat16 g_K[NTOK * DIM];
__device__ __align__(256) __nv_bfloat16 g_V[NTOK * DIM];
__device__ __align__(256) float g_Opart[NSPLIT * NTOK * DIM];
__device__ float g_m[NSPLIT * NTOK];
__device__ float g_l[NSPLIT * NTOK];
__device__ float g_logits[8 * HWD];
__device__ float g_sp[8 * HWD];

// ---------------- PTX helpers ----------------
__device__ __forceinline__ uint32_t smem_u32(const void* p) {
    return (uint32_t)__cvta_generic_to_shared(p);
}
__device__ __forceinline__ void ldsm_x4(uint32_t& r0, uint32_t& r1, uint32_t& r2, uint32_t& r3, uint32_t a) {
    asm volatile("ldmatrix.sync.aligned.m8n8.x4.shared.b16 {%0,%1,%2,%3},[%4];"
                 : "=r"(r0), "=r"(r1), "=r"(r2), "=r"(r3) : "r"(a));
}
__device__ __forceinline__ void ldsm_x4_t(uint32_t& r0, uint32_t& r1, uint32_t& r2, uint32_t& r3, uint32_t a) {
    asm volatile("ldmatrix.sync.aligned.m8n8.x4.trans.shared.b16 {%0,%1,%2,%3},[%4];"
                 : "=r"(r0), "=r"(r1), "=r"(r2), "=r"(r3) : "r"(a));
}
__device__ __forceinline__ void mma16816(float c[4], const uint32_t a[4], uint32_t b0, uint32_t b1) {
    asm volatile("mma.sync.aligned.m16n8k16.row.col.f32.bf16.bf16.f32 "
                 "{%0,%1,%2,%3},{%4,%5,%6,%7},{%8,%9},{%0,%1,%2,%3};"
                 : "+f"(c[0]), "+f"(c[1]), "+f"(c[2]), "+f"(c[3])
                 : "r"(a[0]), "r"(a[1]), "r"(a[2]), "r"(a[3]), "r"(b0), "r"(b1));
}
__device__ __forceinline__ float ex2f(float x) {
    float r; asm("ex2.approx.f32 %0,%1;" : "=f"(r) : "f"(x)); return r;
}
__device__ __forceinline__ uint32_t packbf(float lo, float hi) {
    uint32_t r; asm("cvt.rn.bf16x2.f32 %0,%1,%2;" : "=r"(r) : "f"(hi), "f"(lo)); return r;
}
// packed f32x2 FMA (sm_103a; ptxas never emits from C++)
__device__ __forceinline__ void ffma2(unsigned long long& acc, unsigned long long a, unsigned long long b) {
    asm("fma.rn.f32x2 %0, %1, %2, %0;" : "+l"(acc) : "l"(a), "l"(b));
}
__device__ __forceinline__ unsigned long long bcast2(float v) {
    unsigned long long r; asm("mov.b64 %0, {%1, %1};" : "=l"(r) : "f"(v)); return r;
}
__device__ __forceinline__ float2 unpack2(unsigned long long v) {
    float2 r; asm("mov.b64 {%0, %1}, %2;" : "=f"(r.x), "=f"(r.y) : "l"(v)); return r;
}

// ==================== convert: x -> bf16, W{t,p,a} -> bf16 transposed ====================
__global__ void convert_kernel(const float* __restrict__ x,
                               const float* __restrict__ Wt,
                               const float* __restrict__ Wp,
                               const float* __restrict__ Wa) {
    const int bx = blockIdx.x, tid = threadIdx.x;
    if (bx < 2048) {
        int gid = bx * 256 + tid;              // 524288 threads x 4 elems
        float4 v = *(const float4*)(x + (size_t)gid * 4);
        uint2 p;
        p.x = packbf(v.x, v.y);
        p.y = packbf(v.z, v.w);
        *(uint2*)(g_xb + (size_t)gid * 4) = p;
    } else {
        int i = (bx - 2048) * 256 + tid;       // 0..98303
        int sel = i >> 15;                     // 32768 = 256*128 per W
        int k = i & 255;
        int n = (i >> 8) & 127;
        const float* W = (sel == 0) ? Wt : (sel == 1) ? Wp : Wa;
        g_Wb[sel * 32768 + n * 256 + k] = __float2bfloat16(W[k * 128 + n]);
    }
}

// ==================== proj via tensor cores: g_xb[8192,256] @ Wb^T -> Q/K/V ====================
#define PROWP 264
#define PROJ_SMEM ((64 + 128) * PROWP * 2)

__global__ void __launch_bounds__(128) proj_mma_kernel(const float* __restrict__ bt,
                                                       const float* __restrict__ bp,
                                                       const float* __restrict__ ba) {
    extern __shared__ __align__(16) __nv_bfloat16 psh[];
    __nv_bfloat16* sA = psh;                  // 64 x 256 (pad 264)
    __nv_bfloat16* sB = psh + 64 * PROWP;     // 128 x 256 (pad 264)
    __shared__ float sbias[128];
    const int sel = blockIdx.y;
    const float* bias = (sel == 0) ? bt : (sel == 1) ? bp : ba;
    __nv_bfloat16* dst = (sel == 0) ? g_Q : (sel == 1) ? g_K : g_V;
    const __nv_bfloat16* A = g_xb + (size_t)blockIdx.x * 64 * CIN;
    const __nv_bfloat16* B = g_Wb + (size_t)sel * DIM * CIN;
    const int tid = threadIdx.x, lane = tid & 31, warp = tid >> 5;

    sbias[tid] = bias[tid];  // blockDim==128==DIM

    // A tile: 64 rows x 512B = 32 chunks/row
#pragma unroll
    for (int p = 0; p < 16; ++p) {
        int idx = p * 128 + tid;
        int row = idx >> 5, cc = idx & 31;
        uint32_t d = smem_u32(sA + row * PROWP + cc * 8);
        asm volatile("cp.async.cg.shared.global [%0],[%1],16;" :: "r"(d), "l"(A + row * CIN + cc * 8) : "memory");
    }
    // B tile: 128 rows
#pragma unroll
    for (int p = 0; p < 32; ++p) {
        int idx = p * 128 + tid;
        int row = idx >> 5, cc = idx & 31;
        uint32_t d = smem_u32(sB + row * PROWP + cc * 8);
        asm volatile("cp.async.cg.shared.global [%0],[%1],16;" :: "r"(d), "l"(B + row * CIN + cc * 8) : "memory");
    }
    asm volatile("cp.async.commit_group;" ::: "memory");
    asm volatile("cp.async.wait_group 0;" ::: "memory");
    __syncthreads();

    // A fragments: 16 k-tiles
    uint32_t af[16][4];
    {
        int arow = warp * 16 + (lane & 7) + ((lane & 8) ? 8 : 0);
        int acb = (lane & 16) ? 8 : 0;
#pragma unroll
        for (int kk = 0; kk < 16; ++kk)
            ldsm_x4(af[kk][0], af[kk][1], af[kk][2], af[kk][3],
                    smem_u32(sA + arow * PROWP + kk * 16 + acb));
    }
    float acc[16][4];
#pragma unroll
    for (int n = 0; n < 16; ++n) { acc[n][0] = acc[n][1] = acc[n][2] = acc[n][3] = 0.f; }

    const int brow = (lane & 7) + ((lane & 16) ? 8 : 0);
    const int bc8  = (lane & 8) ? 8 : 0;
#pragma unroll
    for (int kk = 0; kk < 16; ++kk) {
#pragma unroll
        for (int np = 0; np < 8; ++np) {
            uint32_t b0, b1, b2, b3;
            ldsm_x4(b0, b1, b2, b3, smem_u32(sB + (np * 16 + brow) * PROWP + kk * 16 + bc8));
            mma16816(acc[2 * np],     af[kk], b0, b1);
            mma16816(acc[2 * np + 1], af[kk], b2, b3);
        }
    }

    int r0 = blockIdx.x * 64 + warp * 16 + (lane >> 2);
    int c0 = 2 * (lane & 3);
#pragma unroll
    for (int n = 0; n < 16; ++n) {
        int c = n * 8 + c0;
        float b0v = sbias[c], b1v = sbias[c + 1];
        *(uint32_t*)&dst[(size_t)r0 * DIM + c]       = packbf(acc[n][0] + b0v, acc[n][1] + b1v);
        *(uint32_t*)&dst[(size_t)(r0 + 8) * DIM + c] = packbf(acc[n][2] + b0v, acc[n][3] + b1v);
    }
}

// ==================== gate: x @ W_dense (FFMA2, streaming) ====================
__device__ void gate_body(const float* __restrict__ x, const float* __restrict__ Wd,
                          int chunk, float* xs) {
    const int tid = threadIdx.x;
    const int k0 = chunk * 512;
    for (int i = tid; i < 4096; i += 128) {
        int kl = i & 511, b = i >> 9;
        xs[kl * 8 + b] = x[(size_t)b * 262144 + k0 + kl];
    }
    __syncthreads();

    unsigned long long acc[8][4];
#pragma unroll
    for (int b = 0; b < 8; ++b)
#pragma unroll
        for (int c = 0; c < 4; ++c) acc[b][c] = 0ull;

    const int cA = tid * 4, cB = 512 + tid * 4;
#pragma unroll 2
    for (int kl = 0; kl < 512; ++kl) {
        const float* wr = Wd + (size_t)(k0 + kl) * 1024;
        longlong2 wa = __ldcs((const longlong2*)(wr + cA));
        longlong2 wb = __ldcs((const longlong2*)(wr + cB));
        unsigned long long w0 = (unsigned long long)wa.x, w1 = (unsigned long long)wa.y;
        unsigned long long w2 = (unsigned long long)wb.x, w3 = (unsigned long long)wb.y;
        float4 xa = *(const float4*)&xs[kl * 8];
        float4 xb = *(const float4*)&xs[kl * 8 + 4];
        unsigned long long xp;
        xp = bcast2(xa.x); ffma2(acc[0][0], w0, xp); ffma2(acc[0][1], w1, xp); ffma2(acc[0][2], w2, xp); ffma2(acc[0][3], w3, xp);
        xp = bcast2(xa.y); ffma2(acc[1][0], w0, xp); ffma2(acc[1][1], w1, xp); ffma2(acc[1][2], w2, xp); ffma2(acc[1][3], w3, xp);
        xp = bcast2(xa.z); ffma2(acc[2][0], w0, xp); ffma2(acc[2][1], w1, xp); ffma2(acc[2][2], w2, xp); ffma2(acc[2][3], w3, xp);
        xp = bcast2(xa.w); ffma2(acc[3][0], w0, xp); ffma2(acc[3][1], w1, xp); ffma2(acc[3][2], w2, xp); ffma2(acc[3][3], w3, xp);
        xp = bcast2(xb.x); ffma2(acc[4][0], w0, xp); ffma2(acc[4][1], w1, xp); ffma2(acc[4][2], w2, xp); ffma2(acc[4][3], w3, xp);
        xp = bcast2(xb.y); ffma2(acc[5][0], w0, xp); ffma2(acc[5][1], w1, xp); ffma2(acc[5][2], w2, xp); ffma2(acc[5][3], w3, xp);
        xp = bcast2(xb.z); ffma2(acc[6][0], w0, xp); ffma2(acc[6][1], w1, xp); ffma2(acc[6][2], w2, xp); ffma2(acc[6][3], w3, xp);
        xp = bcast2(xb.w); ffma2(acc[7][0], w0, xp); ffma2(acc[7][1], w1, xp); ffma2(acc[7][2], w2, xp); ffma2(acc[7][3], w3, xp);
    }
#pragma unroll
    for (int b = 0; b < 8; ++b) {
        float2 v0 = unpack2(acc[b][0]);
        float2 v1 = unpack2(acc[b][1]);
        float2 v2 = unpack2(acc[b][2]);
        float2 v3 = unpack2(acc[b][3]);
        float* p = g_logits + b * HWD;
        atomicAdd(p + cA + 0, v0.x); atomicAdd(p + cA + 1, v0.y);
        atomicAdd(p + cA + 2, v1.x); atomicAdd(p + cA + 3, v1.y);
        atomicAdd(p + cB + 0, v2.x); atomicAdd(p + cB + 1, v2.y);
        atomicAdd(p + cB + 2, v3.x); atomicAdd(p + cB + 3, v3.y);
    }
}

__global__ void __launch_bounds__(128) gate_kernel(const float* __restrict__ x,
                                                   const float* __restrict__ Wd) {
    __shared__ __align__(16) float xs[4096];
    gate_body(x, Wd, blockIdx.x, xs);
}

__global__ void zero_logits_kernel() {
    g_logits[blockIdx.x * 1024 + threadIdx.x] = 0.f;
}

__global__ void gate_softmax(const float* __restrict__ bd) {
    __shared__ float red[32];
    __shared__ float bc;
    const int b = blockIdx.x, j = threadIdx.x;
    const int lane = j & 31, w = j >> 5;
    float v = g_logits[b * HWD + j] + bd[j];
    float m = v;
#pragma unroll
    for (int o = 16; o; o >>= 1) m = fmaxf(m, __shfl_xor_sync(0xffffffffu, m, o));
    if (lane == 0) red[w] = m;
    __syncthreads();
    if (j < 32) {
        float t = red[j];
#pragma unroll
        for (int o = 16; o; o >>= 1) t = fmaxf(t, __shfl_xor_sync(0xffffffffu, t, o));
        if (j == 0) bc = t;
    }
    __syncthreads();
    float e = expf(v - bc);
    float s = e;
#pragma unroll
    for (int o = 16; o; o >>= 1) s += __shfl_xor_sync(0xffffffffu, s, o);
    if (lane == 0) red[w] = s;
    __syncthreads();
    if (j < 32) {
        float t = red[j];
#pragma unroll
        for (int o = 16; o; o >>= 1) t += __shfl_xor_sync(0xffffffffu, t, o);
        if (j == 0) bc = t;
    }
    __syncthreads();
    g_sp[b * HWD + j] = e / bc;
}

// ==================== flash attention, split-KV x2 (bf16 mma) ====================
#define ROWP 136
#define TILEB (64 * ROWP)
#define FLASH_SMEM (5 * TILEB * 2)

__device__ __forceinline__ void load_tile(__nv_bfloat16* dst, const __nv_bfloat16* src, int tid) {
#pragma unroll
    for (int it = 0; it < 8; ++it) {
        int c = tid + it * 128;
        int row = c >> 4, cc = c & 15;
        uint32_t d = smem_u32(dst + row * ROWP + cc * 8);
        const void* s = src + row * DIM + cc * 8;
        asm volatile("cp.async.cg.shared.global [%0],[%1],16;" :: "r"(d), "l"(s) : "memory");
    }
}

__global__ void __launch_bounds__(128, 2) flash_kernel() {
    extern __shared__ __align__(16) __nv_bfloat16 sh[];
    __nv_bfloat16* sQ = sh;
    __nv_bfloat16* sK = sh + TILEB;
    __nv_bfloat16* sV = sh + 3 * TILEB;
    const int tid = threadIdx.x, lane = tid & 31, warp = tid >> 5;
    const int q0 = blockIdx.x * 64;
    const int split = blockIdx.y;
    const __nv_bfloat16* Kbase = g_K + (size_t)split * KVTILES * 64 * DIM;
    const __nv_bfloat16* Vbase = g_V + (size_t)split * KVTILES * 64 * DIM;

    load_tile(sQ, g_Q + (size_t)q0 * DIM, tid);
    asm volatile("cp.async.commit_group;" ::: "memory");
    load_tile(sK, Kbase, tid);
    load_tile(sV, Vbase, tid);
    asm volatile("cp.async.commit_group;" ::: "memory");
    asm volatile("cp.async.wait_group 1;" ::: "memory");
    __syncthreads();

    uint32_t qf[8][4];
    {
        int row = warp * 16 + (lane & 7) + ((lane & 8) ? 8 : 0);
        int cb = (lane & 16) ? 8 : 0;
#pragma unroll
        for (int kk = 0; kk < 8; ++kk)
            ldsm_x4(qf[kk][0], qf[kk][1], qf[kk][2], qf[kk][3],
                    smem_u32(sQ + row * ROWP + kk * 16 + cb));
    }

    float oacc[16][4];
#pragma unroll
    for (int n = 0; n < 16; ++n) { oacc[n][0] = oacc[n][1] = oacc[n][2] = oacc[n][3] = 0.f; }
    float m0 = -1e30f, m1 = -1e30f, l0 = 0.f, l1 = 0.f;

    const int krow = (lane & 7) + ((lane & 16) ? 8 : 0);
    const int kc8  = (lane & 8) ? 8 : 0;
    const int vrow = (lane & 7) + ((lane & 8) ? 8 : 0);
    const int vc8  = (lane & 16) ? 8 : 0;

    for (int t = 0; t < KVTILES; ++t) {
        const int buf = t & 1;
        if (t < KVTILES - 1) {
            load_tile(sK + (1 - buf) * TILEB, Kbase + (size_t)(t + 1) * 64 * DIM, tid);
            load_tile(sV + (1 - buf) * TILEB, Vbase + (size_t)(t + 1) * 64 * DIM, tid);
        }
        asm volatile("cp.async.commit_group;" ::: "memory");
        asm volatile("cp.async.wait_group 1;" ::: "memory");
        __syncthreads();
        const __nv_bfloat16* kb = sK + buf * TILEB;
        const __nv_bfloat16* vb = sV + buf * TILEB;

        float sacc[8][4];
#pragma unroll
        for (int n = 0; n < 8; ++n) { sacc[n][0] = sacc[n][1] = sacc[n][2] = sacc[n][3] = 0.f; }
#pragma unroll
        for (int kk = 0; kk < 8; ++kk) {
#pragma unroll
            for (int np = 0; np < 4; ++np) {
                uint32_t b0, b1, b2, b3;
                ldsm_x4(b0, b1, b2, b3, smem_u32(kb + (np * 16 + krow) * ROWP + kk * 16 + kc8));
                mma16816(sacc[2 * np],     qf[kk], b0, b1);
                mma16816(sacc[2 * np + 1], qf[kk], b2, b3);
            }
        }

        float mx0 = -1e30f, mx1 = -1e30f;
#pragma unroll
        for (int n = 0; n < 8; ++n) {
            mx0 = fmaxf(mx0, fmaxf(sacc[n][0], sacc[n][1]));
            mx1 = fmaxf(mx1, fmaxf(sacc[n][2], sacc[n][3]));
        }
        mx0 = fmaxf(mx0, __shfl_xor_sync(0xffffffffu, mx0, 1));
        mx0 = fmaxf(mx0, __shfl_xor_sync(0xffffffffu, mx0, 2));
        mx1 = fmaxf(mx1, __shfl_xor_sync(0xffffffffu, mx1, 1));
        mx1 = fmaxf(mx1, __shfl_xor_sync(0xffffffffu, mx1, 2));
        float mn0 = fmaxf(m0, mx0), mn1 = fmaxf(m1, mx1);
        float sc0 = ex2f((m0 - mn0) * LOG2E), sc1 = ex2f((m1 - mn1) * LOG2E);
        float rs0 = 0.f, rs1 = 0.f;
#pragma unroll
        for (int n = 0; n < 8; ++n) {
            sacc[n][0] = ex2f((sacc[n][0] - mn0) * LOG2E);
            sacc[n][1] = ex2f((sacc[n][1] - mn0) * LOG2E);
            sacc[n][2] = ex2f((sacc[n][2] - mn1) * LOG2E);
            sacc[n][3] = ex2f((sacc[n][3] - mn1) * LOG2E);
            rs0 += sacc[n][0] + sacc[n][1];
            rs1 += sacc[n][2] + sacc[n][3];
        }
        rs0 += __shfl_xor_sync(0xffffffffu, rs0, 1);
        rs0 += __shfl_xor_sync(0xffffffffu, rs0, 2);
        rs1 += __shfl_xor_sync(0xffffffffu, rs1, 1);
        rs1 += __shfl_xor_sync(0xffffffffu, rs1, 2);
        l0 = l0 * sc0 + rs0; l1 = l1 * sc1 + rs1;
        m0 = mn0; m1 = mn1;
#pragma unroll
        for (int n = 0; n < 16; ++n) {
            oacc[n][0] *= sc0; oacc[n][1] *= sc0;
            oacc[n][2] *= sc1; oacc[n][3] *= sc1;
        }

        uint32_t pf[4][4];
#pragma unroll
        for (int i = 0; i < 4; ++i) {
            pf[i][0] = packbf(sacc[2 * i][0],     sacc[2 * i][1]);
            pf[i][1] = packbf(sacc[2 * i][2],     sacc[2 * i][3]);
            pf[i][2] = packbf(sacc[2 * i + 1][0], sacc[2 * i + 1][1]);
            pf[i][3] = packbf(sacc[2 * i + 1][2], sacc[2 * i + 1][3]);
        }

#pragma unroll
        for (int i = 0; i < 4; ++i) {
#pragma unroll
            for (int np = 0; np < 8; ++np) {
                uint32_t b0, b1, b2, b3;
                ldsm_x4_t(b0, b1, b2, b3, smem_u32(vb + (i * 16 + vrow) * ROWP + np * 16 + vc8));
                mma16816(oacc[2 * np],     pf[i], b0, b1);
                mma16816(oacc[2 * np + 1], pf[i], b2, b3);
            }
        }
        __syncthreads();
    }

    float* Op = g_Opart + (size_t)split * NTOK * DIM;
    int row0 = q0 + warp * 16 + (lane >> 2);
    int c0 = 2 * (lane & 3);
#pragma unroll
    for (int n = 0; n < 16; ++n) {
        int c = n * 8 + c0;
        *(float2*)&Op[(size_t)row0 * DIM + c]       = make_float2(oacc[n][0], oacc[n][1]);
        *(float2*)&Op[(size_t)(row0 + 8) * DIM + c] = make_float2(oacc[n][2], oacc[n][3]);
    }
    if ((lane & 3) == 0) {
        g_m[split * NTOK + row0] = m0;     g_l[split * NTOK + row0] = l0;
        g_m[split * NTOK + row0 + 8] = m1; g_l[split * NTOK + row0 + 8] = l1;
    }
}

// ==================== epilogue: combine splits, (O @ W_mask) * sp + x ====================
__global__ void epilogue_kernel(const float* __restrict__ x, const float* __restrict__ Wm,
                                float* __restrict__ out) {
    __shared__ float4 sO[32 * 32];
    __shared__ float ssp[32], sw0[32], sw1[32], sinv[32];
    const int tid = threadIdx.x;
    const int t0 = blockIdx.x * 32;
    if (tid < 32) {
        int r = t0 + tid;
        float m0 = g_m[r], m1 = g_m[NTOK + r];
        float l0 = g_l[r], l1 = g_l[NTOK + r];
        float mm = fmaxf(m0, m1);
        float w0 = ex2f((m0 - mm) * LOG2E), w1 = ex2f((m1 - mm) * LOG2E);
        sw0[tid] = w0; sw1[tid] = w1;
        sinv[tid] = 1.f / (l0 * w0 + l1 * w1);
        ssp[tid] = g_sp[r];
    }
    __syncthreads();
    const float4* o0 = (const float4*)(g_Opart + (size_t)t0 * DIM);
    const float4* o1 = (const float4*)(g_Opart + (size_t)NTOK * DIM + (size_t)t0 * DIM);
    for (int i = tid; i < 1024; i += 256) {
        int t = i >> 5;
        float w0 = sw0[t] * sinv[t], w1 = sw1[t] * sinv[t];
        float4 a = o0[i], b = o1[i];
        sO[i] = make_float4(a.x * w0 + b.x * w1, a.y * w0 + b.y * w1,
                            a.z * w0 + b.z * w1, a.w * w0 + b.w * w1);
    }
    __syncthreads();
    const int j = tid;
    float acc[32];
#pragma unroll
    for (int t = 0; t < 32; ++t) acc[t] = 0.f;
    for (int k4 = 0; k4 < 32; ++k4) {
        float w0 = Wm[(k4 * 4 + 0) * CIN + j];
        float w1 = Wm[(k4 * 4 + 1) * CIN + j];
        float w2 = Wm[(k4 * 4 + 2) * CIN + j];
        float w3 = Wm[(k4 * 4 + 3) * CIN + j];
#pragma unroll
        for (int t = 0; t < 32; ++t) {
            float4 v = sO[t * 32 + k4];
            acc[t] = fmaf(v.x, w0, acc[t]);
            acc[t] = fmaf(v.y, w1, acc[t]);
            acc[t] = fmaf(v.z, w2, acc[t]);
            acc[t] = fmaf(v.w, w3, acc[t]);
        }
    }
#pragma unroll
    for (int t = 0; t < 32; ++t)
        out[(size_t)(t0 + t) * CIN + j] = acc[t] * ssp[t] + x[(size_t)(t0 + t) * CIN + j];
}

// ==================== launcher ====================
extern "C" void kernel_launch(void* const* d_in, const int* in_sizes, int n_in,
                              void* d_out, int out_size) {
    const float* x  = (const float*)d_in[0];
    const float* Wt = (const float*)d_in[1];
    const float* bt = (const float*)d_in[2];
    const float* Wp = (const float*)d_in[3];
    const float* bp = (const float*)d_in[4];
    const float* Wa = (const float*)d_in[5];
    const float* ba = (const float*)d_in[6];
    const float* Wm = (const float*)d_in[7];
    const float* Wd = (const float*)d_in[8];
    const float* bd = (const float*)d_in[9];
    float* out = (float*)d_out;

    cudaFuncSetAttribute(flash_kernel, cudaFuncAttributeMaxDynamicSharedMemorySize, FLASH_SMEM);
    cudaFuncSetAttribute(proj_mma_kernel, cudaFuncAttributeMaxDynamicSharedMemorySize, PROJ_SMEM);

    convert_kernel<<<2432, 256>>>(x, Wt, Wp, Wa);                 // 1
    zero_logits_kernel<<<8, 1024>>>();                            // 2
    proj_mma_kernel<<<dim3(128, 3), 128, PROJ_SMEM>>>(bt, bp, ba);// 3
    gate_kernel<<<512, 128>>>(x, Wd);                             // 4  (ncu shows this one)
    flash_kernel<<<dim3(128, NSPLIT), 128, FLASH_SMEM>>>();       // 5
    gate_softmax<<<8, 1024>>>(bd);                                // 6
    epilogue_kernel<<<256, 256>>>(x, Wm, out);                    // 7
}

// round 15
// speedup vs baseline: 1.3670x; 1.0727x over previous
#include <cuda_runtime.h>
#include <cuda_bf16.h>
#include <cstdint>

#define NTOK 8192
#define DIM  128
#define CIN  256
#define HWD  1024
#define LOG2E 1.4426950408889634f
#define NSPLIT 2
#define KVTILES 64
#define GATE_CHUNKS 512      // 512 chunks x 512 k-rows

// ---------------- device workspaces ----------------
__device__ __align__(256) __nv_bfloat16 g_xb[NTOK * CIN];
__device__ __align__(256) __nv_bfloat16 g_Wb[3 * DIM * CIN];   // W^T bf16 [sel][n][k]
__device__ __align__(256) __nv_bfloat16 g_Q[NTOK * DIM];
__device__ __align__(256) __nv_bfloat16 g_K[NTOK * DIM];
__device__ __align__(256) __nv_bfloat16 g_V[NTOK * DIM];
__device__ __align__(256) float g_Opart[NSPLIT * NTOK * DIM];
__device__ float g_m[NSPLIT * NTOK];
__device__ float g_l[NSPLIT * NTOK];
__device__ float g_logits[8 * HWD];
__device__ float g_sp[8 * HWD];

// ---------------- PTX helpers ----------------
__device__ __forceinline__ uint32_t smem_u32(const void* p) {
    return (uint32_t)__cvta_generic_to_shared(p);
}
__device__ __forceinline__ void ldsm_x4(uint32_t& r0, uint32_t& r1, uint32_t& r2, uint32_t& r3, uint32_t a) {
    asm volatile("ldmatrix.sync.aligned.m8n8.x4.shared.b16 {%0,%1,%2,%3},[%4];"
                 : "=r"(r0), "=r"(r1), "=r"(r2), "=r"(r3) : "r"(a));
}
__device__ __forceinline__ void ldsm_x4_t(uint32_t& r0, uint32_t& r1, uint32_t& r2, uint32_t& r3, uint32_t a) {
    asm volatile("ldmatrix.sync.aligned.m8n8.x4.trans.shared.b16 {%0,%1,%2,%3},[%4];"
                 : "=r"(r0), "=r"(r1), "=r"(r2), "=r"(r3) : "r"(a));
}
__device__ __forceinline__ void mma16816(float c[4], const uint32_t a[4], uint32_t b0, uint32_t b1) {
    asm volatile("mma.sync.aligned.m16n8k16.row.col.f32.bf16.bf16.f32 "
                 "{%0,%1,%2,%3},{%4,%5,%6,%7},{%8,%9},{%0,%1,%2,%3};"
                 : "+f"(c[0]), "+f"(c[1]), "+f"(c[2]), "+f"(c[3])
                 : "r"(a[0]), "r"(a[1]), "r"(a[2]), "r"(a[3]), "r"(b0), "r"(b1));
}
__device__ __forceinline__ float ex2f(float x) {
    float r; asm("ex2.approx.f32 %0,%1;" : "=f"(r) : "f"(x)); return r;
}
__device__ __forceinline__ uint32_t packbf(float lo, float hi) {
    uint32_t r; asm("cvt.rn.bf16x2.f32 %0,%1,%2;" : "=r"(r) : "f"(hi), "f"(lo)); return r;
}
__device__ __forceinline__ void ffma2(unsigned long long& acc, unsigned long long a, unsigned long long b) {
    asm("fma.rn.f32x2 %0, %1, %2, %0;" : "+l"(acc) : "l"(a), "l"(b));
}
__device__ __forceinline__ unsigned long long bcast2(float v) {
    unsigned long long r; asm("mov.b64 %0, {%1, %1};" : "=l"(r) : "f"(v)); return r;
}
__device__ __forceinline__ float2 unpack2(unsigned long long v) {
    float2 r; asm("mov.b64 {%0, %1}, %2;" : "=f"(r.x), "=f"(r.y) : "l"(v)); return r;
}

// ==================== convert: x -> bf16, W{t,p,a} -> bf16 transposed ====================
__global__ void convert_kernel(const float* __restrict__ x,
                               const float* __restrict__ Wt,
                               const float* __restrict__ Wp,
                               const float* __restrict__ Wa) {
    const int bx = blockIdx.x, tid = threadIdx.x;
    if (bx < 2048) {
        int gid = bx * 256 + tid;
        float4 v = *(const float4*)(x + (size_t)gid * 4);
        uint2 p;
        p.x = packbf(v.x, v.y);
        p.y = packbf(v.z, v.w);
        *(uint2*)(g_xb + (size_t)gid * 4) = p;
    } else {
        int i = (bx - 2048) * 256 + tid;
        int sel = i >> 15;
        int k = i & 255;
        int n = (i >> 8) & 127;
        const float* W = (sel == 0) ? Wt : (sel == 1) ? Wp : Wa;
        g_Wb[sel * 32768 + n * 256 + k] = __float2bfloat16(W[k * 128 + n]);
    }
}

// ==================== proj via tensor cores ====================
#define PROWP 264
#define PROJ_SMEM ((64 + 128) * PROWP * 2)

__global__ void __launch_bounds__(128) proj_mma_kernel(const float* __restrict__ bt,
                                                       const float* __restrict__ bp,
                                                       const float* __restrict__ ba) {
    extern __shared__ __align__(16) __nv_bfloat16 psh[];
    __nv_bfloat16* sA = psh;
    __nv_bfloat16* sB = psh + 64 * PROWP;
    __shared__ float sbias[128];
    const int sel = blockIdx.y;
    const float* bias = (sel == 0) ? bt : (sel == 1) ? bp : ba;
    __nv_bfloat16* dst = (sel == 0) ? g_Q : (sel == 1) ? g_K : g_V;
    const __nv_bfloat16* A = g_xb + (size_t)blockIdx.x * 64 * CIN;
    const __nv_bfloat16* B = g_Wb + (size_t)sel * DIM * CIN;
    const int tid = threadIdx.x, lane = tid & 31, warp = tid >> 5;

    sbias[tid] = bias[tid];

#pragma unroll
    for (int p = 0; p < 16; ++p) {
        int idx = p * 128 + tid;
        int row = idx >> 5, cc = idx & 31;
        uint32_t d = smem_u32(sA + row * PROWP + cc * 8);
        asm volatile("cp.async.cg.shared.global [%0],[%1],16;" :: "r"(d), "l"(A + row * CIN + cc * 8) : "memory");
    }
#pragma unroll
    for (int p = 0; p < 32; ++p) {
        int idx = p * 128 + tid;
        int row = idx >> 5, cc = idx & 31;
        uint32_t d = smem_u32(sB + row * PROWP + cc * 8);
        asm volatile("cp.async.cg.shared.global [%0],[%1],16;" :: "r"(d), "l"(B + row * CIN + cc * 8) : "memory");
    }
    asm volatile("cp.async.commit_group;" ::: "memory");
    asm volatile("cp.async.wait_group 0;" ::: "memory");
    __syncthreads();

    uint32_t af[16][4];
    {
        int arow = warp * 16 + (lane & 7) + ((lane & 8) ? 8 : 0);
        int acb = (lane & 16) ? 8 : 0;
#pragma unroll
        for (int kk = 0; kk < 16; ++kk)
            ldsm_x4(af[kk][0], af[kk][1], af[kk][2], af[kk][3],
                    smem_u32(sA + arow * PROWP + kk * 16 + acb));
    }
    float acc[16][4];
#pragma unroll
    for (int n = 0; n < 16; ++n) { acc[n][0] = acc[n][1] = acc[n][2] = acc[n][3] = 0.f; }

    const int brow = (lane & 7) + ((lane & 16) ? 8 : 0);
    const int bc8  = (lane & 8) ? 8 : 0;
#pragma unroll
    for (int kk = 0; kk < 16; ++kk) {
#pragma unroll
        for (int np = 0; np < 8; ++np) {
            uint32_t b0, b1, b2, b3;
            ldsm_x4(b0, b1, b2, b3, smem_u32(sB + (np * 16 + brow) * PROWP + kk * 16 + bc8));
            mma16816(acc[2 * np],     af[kk], b0, b1);
            mma16816(acc[2 * np + 1], af[kk], b2, b3);
        }
    }

    int r0 = blockIdx.x * 64 + warp * 16 + (lane >> 2);
    int c0 = 2 * (lane & 3);
#pragma unroll
    for (int n = 0; n < 16; ++n) {
        int c = n * 8 + c0;
        float b0v = sbias[c], b1v = sbias[c + 1];
        *(uint32_t*)&dst[(size_t)r0 * DIM + c]       = packbf(acc[n][0] + b0v, acc[n][1] + b1v);
        *(uint32_t*)&dst[(size_t)(r0 + 8) * DIM + c] = packbf(acc[n][2] + b0v, acc[n][3] + b1v);
    }
}

// ==================== gate body (FFMA2, streaming, unroll 4) ====================
__device__ void gate_body(const float* __restrict__ x, const float* __restrict__ Wd,
                          int chunk, float* xs) {
    const int tid = threadIdx.x;
    const int k0 = chunk * 512;
    for (int i = tid; i < 4096; i += 128) {
        int kl = i & 511, b = i >> 9;
        xs[kl * 8 + b] = x[(size_t)b * 262144 + k0 + kl];
    }
    __syncthreads();

    unsigned long long acc[8][4];
#pragma unroll
    for (int b = 0; b < 8; ++b)
#pragma unroll
        for (int c = 0; c < 4; ++c) acc[b][c] = 0ull;

    const int cA = tid * 4, cB = 512 + tid * 4;
#pragma unroll 4
    for (int kl = 0; kl < 512; ++kl) {
        const float* wr = Wd + (size_t)(k0 + kl) * 1024;
        longlong2 wa = __ldcs((const longlong2*)(wr + cA));
        longlong2 wb = __ldcs((const longlong2*)(wr + cB));
        unsigned long long w0 = (unsigned long long)wa.x, w1 = (unsigned long long)wa.y;
        unsigned long long w2 = (unsigned long long)wb.x, w3 = (unsigned long long)wb.y;
        float4 xa = *(const float4*)&xs[kl * 8];
        float4 xb = *(const float4*)&xs[kl * 8 + 4];
        unsigned long long xp;
        xp = bcast2(xa.x); ffma2(acc[0][0], w0, xp); ffma2(acc[0][1], w1, xp); ffma2(acc[0][2], w2, xp); ffma2(acc[0][3], w3, xp);
        xp = bcast2(xa.y); ffma2(acc[1][0], w0, xp); ffma2(acc[1][1], w1, xp); ffma2(acc[1][2], w2, xp); ffma2(acc[1][3], w3, xp);
        xp = bcast2(xa.z); ffma2(acc[2][0], w0, xp); ffma2(acc[2][1], w1, xp); ffma2(acc[2][2], w2, xp); ffma2(acc[2][3], w3, xp);
        xp = bcast2(xa.w); ffma2(acc[3][0], w0, xp); ffma2(acc[3][1], w1, xp); ffma2(acc[3][2], w2, xp); ffma2(acc[3][3], w3, xp);
        xp = bcast2(xb.x); ffma2(acc[4][0], w0, xp); ffma2(acc[4][1], w1, xp); ffma2(acc[4][2], w2, xp); ffma2(acc[4][3], w3, xp);
        xp = bcast2(xb.y); ffma2(acc[5][0], w0, xp); ffma2(acc[5][1], w1, xp); ffma2(acc[5][2], w2, xp); ffma2(acc[5][3], w3, xp);
        xp = bcast2(xb.z); ffma2(acc[6][0], w0, xp); ffma2(acc[6][1], w1, xp); ffma2(acc[6][2], w2, xp); ffma2(acc[6][3], w3, xp);
        xp = bcast2(xb.w); ffma2(acc[7][0], w0, xp); ffma2(acc[7][1], w1, xp); ffma2(acc[7][2], w2, xp); ffma2(acc[7][3], w3, xp);
    }
#pragma unroll
    for (int b = 0; b < 8; ++b) {
        float2 v0 = unpack2(acc[b][0]);
        float2 v1 = unpack2(acc[b][1]);
        float2 v2 = unpack2(acc[b][2]);
        float2 v3 = unpack2(acc[b][3]);
        float* p = g_logits + b * HWD;
        atomicAdd(p + cA + 0, v0.x); atomicAdd(p + cA + 1, v0.y);
        atomicAdd(p + cA + 2, v1.x); atomicAdd(p + cA + 3, v1.y);
        atomicAdd(p + cB + 0, v2.x); atomicAdd(p + cB + 1, v2.y);
        atomicAdd(p + cB + 2, v3.x); atomicAdd(p + cB + 3, v3.y);
    }
}

// ==================== fat kernel: flash (even bids < 512) + gate (others) ====================
#define ROWP 136
#define TILEB (64 * ROWP)
#define FLASH_SMEM (5 * TILEB * 2)

__device__ __forceinline__ void load_tile(__nv_bfloat16* dst, const __nv_bfloat16* src, int tid) {
#pragma unroll
    for (int it = 0; it < 8; ++it) {
        int c = tid + it * 128;
        int row = c >> 4, cc = c & 15;
        uint32_t d = smem_u32(dst + row * ROWP + cc * 8);
        const void* s = src + row * DIM + cc * 8;
        asm volatile("cp.async.cg.shared.global [%0],[%1],16;" :: "r"(d), "l"(s) : "memory");
    }
}

__global__ void __launch_bounds__(128, 2) fat_kernel(const float* __restrict__ x,
                                                     const float* __restrict__ Wd) {
    extern __shared__ __align__(16) __nv_bfloat16 sh[];
    const int bid = blockIdx.x;

    // bids 0..511: even -> flash(fidx=bid/2), odd -> gate(chunk=bid/2)
    // bids 512..767: gate(chunk=256+bid-512)
    if (bid >= 512 || (bid & 1)) {
        int chunk = (bid >= 512) ? (256 + bid - 512) : (bid >> 1);
        gate_body(x, Wd, chunk, (float*)sh);
        return;
    }
    const int fidx = bid >> 1;                // 0..255
    const int q0 = (fidx >> 1) * 64;
    const int split = fidx & 1;

    __nv_bfloat16* sQ = sh;
    __nv_bfloat16* sK = sh + TILEB;
    __nv_bfloat16* sV = sh + 3 * TILEB;
    const int tid = threadIdx.x, lane = tid & 31, warp = tid >> 5;
    const __nv_bfloat16* Kbase = g_K + (size_t)split * KVTILES * 64 * DIM;
    const __nv_bfloat16* Vbase = g_V + (size_t)split * KVTILES * 64 * DIM;

    load_tile(sQ, g_Q + (size_t)q0 * DIM, tid);
    asm volatile("cp.async.commit_group;" ::: "memory");
    load_tile(sK, Kbase, tid);
    load_tile(sV, Vbase, tid);
    asm volatile("cp.async.commit_group;" ::: "memory");
    asm volatile("cp.async.wait_group 1;" ::: "memory");
    __syncthreads();

    uint32_t qf[8][4];
    {
        int row = warp * 16 + (lane & 7) + ((lane & 8) ? 8 : 0);
        int cb = (lane & 16) ? 8 : 0;
#pragma unroll
        for (int kk = 0; kk < 8; ++kk)
            ldsm_x4(qf[kk][0], qf[kk][1], qf[kk][2], qf[kk][3],
                    smem_u32(sQ + row * ROWP + kk * 16 + cb));
    }

    float oacc[16][4];
#pragma unroll
    for (int n = 0; n < 16; ++n) { oacc[n][0] = oacc[n][1] = oacc[n][2] = oacc[n][3] = 0.f; }
    float m0 = -1e30f, m1 = -1e30f, l0 = 0.f, l1 = 0.f;

    const int krow = (lane & 7) + ((lane & 16) ? 8 : 0);
    const int kc8  = (lane & 8) ? 8 : 0;
    const int vrow = (lane & 7) + ((lane & 8) ? 8 : 0);
    const int vc8  = (lane & 16) ? 8 : 0;

    for (int t = 0; t < KVTILES; ++t) {
        const int buf = t & 1;
        if (t < KVTILES - 1) {
            load_tile(sK + (1 - buf) * TILEB, Kbase + (size_t)(t + 1) * 64 * DIM, tid);
            load_tile(sV + (1 - buf) * TILEB, Vbase + (size_t)(t + 1) * 64 * DIM, tid);
        }
        asm volatile("cp.async.commit_group;" ::: "memory");
        asm volatile("cp.async.wait_group 1;" ::: "memory");
        __syncthreads();
        const __nv_bfloat16* kb = sK + buf * TILEB;
        const __nv_bfloat16* vb = sV + buf * TILEB;

        float sacc[8][4];
#pragma unroll
        for (int n = 0; n < 8; ++n) { sacc[n][0] = sacc[n][1] = sacc[n][2] = sacc[n][3] = 0.f; }
#pragma unroll
        for (int kk = 0; kk < 8; ++kk) {
#pragma unroll
            for (int np = 0; np < 4; ++np) {
                uint32_t b0, b1, b2, b3;
                ldsm_x4(b0, b1, b2, b3, smem_u32(kb + (np * 16 + krow) * ROWP + kk * 16 + kc8));
                mma16816(sacc[2 * np],     qf[kk], b0, b1);
                mma16816(sacc[2 * np + 1], qf[kk], b2, b3);
            }
        }

        float mx0 = -1e30f, mx1 = -1e30f;
#pragma unroll
        for (int n = 0; n < 8; ++n) {
            mx0 = fmaxf(mx0, fmaxf(sacc[n][0], sacc[n][1]));
            mx1 = fmaxf(mx1, fmaxf(sacc[n][2], sacc[n][3]));
        }
        mx0 = fmaxf(mx0, __shfl_xor_sync(0xffffffffu, mx0, 1));
        mx0 = fmaxf(mx0, __shfl_xor_sync(0xffffffffu, mx0, 2));
        mx1 = fmaxf(mx1, __shfl_xor_sync(0xffffffffu, mx1, 1));
        mx1 = fmaxf(mx1, __shfl_xor_sync(0xffffffffu, mx1, 2));
        float mn0 = fmaxf(m0, mx0), mn1 = fmaxf(m1, mx1);
        float sc0 = ex2f((m0 - mn0) * LOG2E), sc1 = ex2f((m1 - mn1) * LOG2E);
        float rs0 = 0.f, rs1 = 0.f;
#pragma unroll
        for (int n = 0; n < 8; ++n) {
            sacc[n][0] = ex2f((sacc[n][0] - mn0) * LOG2E);
            sacc[n][1] = ex2f((sacc[n][1] - mn0) * LOG2E);
            sacc[n][2] = ex2f((sacc[n][2] - mn1) * LOG2E);
            sacc[n][3] = ex2f((sacc[n][3] - mn1) * LOG2E);
            rs0 += sacc[n][0] + sacc[n][1];
            rs1 += sacc[n][2] + sacc[n][3];
        }
        rs0 += __shfl_xor_sync(0xffffffffu, rs0, 1);
        rs0 += __shfl_xor_sync(0xffffffffu, rs0, 2);
        rs1 += __shfl_xor_sync(0xffffffffu, rs1, 1);
        rs1 += __shfl_xor_sync(0xffffffffu, rs1, 2);
        l0 = l0 * sc0 + rs0; l1 = l1 * sc1 + rs1;
        m0 = mn0; m1 = mn1;
#pragma unroll
        for (int n = 0; n < 16; ++n) {
            oacc[n][0] *= sc0; oacc[n][1] *= sc0;
            oacc[n][2] *= sc1; oacc[n][3] *= sc1;
        }

        uint32_t pf[4][4];
#pragma unroll
        for (int i = 0; i < 4; ++i) {
            pf[i][0] = packbf(sacc[2 * i][0],     sacc[2 * i][1]);
            pf[i][1] = packbf(sacc[2 * i][2],     sacc[2 * i][3]);
            pf[i][2] = packbf(sacc[2 * i + 1][0], sacc[2 * i + 1][1]);
            pf[i][3] = packbf(sacc[2 * i + 1][2], sacc[2 * i + 1][3]);
        }

#pragma unroll
        for (int i = 0; i < 4; ++i) {
#pragma unroll
            for (int np = 0; np < 8; ++np) {
                uint32_t b0, b1, b2, b3;
                ldsm_x4_t(b0, b1, b2, b3, smem_u32(vb + (i * 16 + vrow) * ROWP + np * 16 + vc8));
                mma16816(oacc[2 * np],     pf[i], b0, b1);
                mma16816(oacc[2 * np + 1], pf[i], b2, b3);
            }
        }
        __syncthreads();
    }

    float* Op = g_Opart + (size_t)split * NTOK * DIM;
    int row0 = q0 + warp * 16 + (lane >> 2);
    int c0 = 2 * (lane & 3);
#pragma unroll
    for (int n = 0; n < 16; ++n) {
        int c = n * 8 + c0;
        *(float2*)&Op[(size_t)row0 * DIM + c]       = make_float2(oacc[n][0], oacc[n][1]);
        *(float2*)&Op[(size_t)(row0 + 8) * DIM + c] = make_float2(oacc[n][2], oacc[n][3]);
    }
    if ((lane & 3) == 0) {
        g_m[split * NTOK + row0] = m0;     g_l[split * NTOK + row0] = l0;
        g_m[split * NTOK + row0 + 8] = m1; g_l[split * NTOK + row0 + 8] = l1;
    }
}

// ==================== small kernels ====================
__global__ void zero_logits_kernel() {
    g_logits[blockIdx.x * 1024 + threadIdx.x] = 0.f;
}

__global__ void gate_softmax(const float* __restrict__ bd) {
    __shared__ float red[32];
    __shared__ float bc;
    const int b = blockIdx.x, j = threadIdx.x;
    const int lane = j & 31, w = j >> 5;
    float v = g_logits[b * HWD + j] + bd[j];
    float m = v;
#pragma unroll
    for (int o = 16; o; o >>= 1) m = fmaxf(m, __shfl_xor_sync(0xffffffffu, m, o));
    if (lane == 0) red[w] = m;
    __syncthreads();
    if (j < 32) {
        float t = red[j];
#pragma unroll
        for (int o = 16; o; o >>= 1) t = fmaxf(t, __shfl_xor_sync(0xffffffffu, t, o));
        if (j == 0) bc = t;
    }
    __syncthreads();
    float e = expf(v - bc);
    float s = e;
#pragma unroll
    for (int o = 16; o; o >>= 1) s += __shfl_xor_sync(0xffffffffu, s, o);
    if (lane == 0) red[w] = s;
    __syncthreads();
    if (j < 32) {
        float t = red[j];
#pragma unroll
        for (int o = 16; o; o >>= 1) t += __shfl_xor_sync(0xffffffffu, t, o);
        if (j == 0) bc = t;
    }
    __syncthreads();
    g_sp[b * HWD + j] = e / bc;
}

// ==================== epilogue ====================
__global__ void epilogue_kernel(const float* __restrict__ x, const float* __restrict__ Wm,
                                float* __restrict__ out) {
    __shared__ float4 sO[32 * 32];
    __shared__ float ssp[32], sw0[32], sw1[32], sinv[32];
    const int tid = threadIdx.x;
    const int t0 = blockIdx.x * 32;
    if (tid < 32) {
        int r = t0 + tid;
        float m0 = g_m[r], m1 = g_m[NTOK + r];
        float l0 = g_l[r], l1 = g_l[NTOK + r];
        float mm = fmaxf(m0, m1);
        float w0 = ex2f((m0 - mm) * LOG2E), w1 = ex2f((m1 - mm) * LOG2E);
        sw0[tid] = w0; sw1[tid] = w1;
        sinv[tid] = 1.f / (l0 * w0 + l1 * w1);
        ssp[tid] = g_sp[r];
    }
    __syncthreads();
    const float4* o0 = (const float4*)(g_Opart + (size_t)t0 * DIM);
    const float4* o1 = (const float4*)(g_Opart + (size_t)NTOK * DIM + (size_t)t0 * DIM);
    for (int i = tid; i < 1024; i += 256) {
        int t = i >> 5;
        float w0 = sw0[t] * sinv[t], w1 = sw1[t] * sinv[t];
        float4 a = o0[i], b = o1[i];
        sO[i] = make_float4(a.x * w0 + b.x * w1, a.y * w0 + b.y * w1,
                            a.z * w0 + b.z * w1, a.w * w0 + b.w * w1);
    }
    __syncthreads();
    const int j = tid;
    float acc[32];
#pragma unroll
    for (int t = 0; t < 32; ++t) acc[t] = 0.f;
    for (int k4 = 0; k4 < 32; ++k4) {
        float w0 = Wm[(k4 * 4 + 0) * CIN + j];
        float w1 = Wm[(k4 * 4 + 1) * CIN + j];
        float w2 = Wm[(k4 * 4 + 2) * CIN + j];
        float w3 = Wm[(k4 * 4 + 3) * CIN + j];
#pragma unroll
        for (int t = 0; t < 32; ++t) {
            float4 v = sO[t * 32 + k4];
            acc[t] = fmaf(v.x, w0, acc[t]);
            acc[t] = fmaf(v.y, w1, acc[t]);
            acc[t] = fmaf(v.z, w2, acc[t]);
            acc[t] = fmaf(v.w, w3, acc[t]);
        }
    }
#pragma unroll
    for (int t = 0; t < 32; ++t)
        out[(size_t)(t0 + t) * CIN + j] = acc[t] * ssp[t] + x[(size_t)(t0 + t) * CIN + j];
}

// ==================== launcher ====================
extern "C" void kernel_launch(void* const* d_in, const int* in_sizes, int n_in,
                              void* d_out, int out_size) {
    const float* x  = (const float*)d_in[0];
    const float* Wt = (const float*)d_in[1];
    const float* bt = (const float*)d_in[2];
    const float* Wp = (const float*)d_in[3];
    const float* bp = (const float*)d_in[4];
    const float* Wa = (const float*)d_in[5];
    const float* ba = (const float*)d_in[6];
    const float* Wm = (const float*)d_in[7];
    const float* Wd = (const float*)d_in[8];
    const float* bd = (const float*)d_in[9];
    float* out = (float*)d_out;

    cudaFuncSetAttribute(fat_kernel, cudaFuncAttributeMaxDynamicSharedMemorySize, FLASH_SMEM);
    cudaFuncSetAttribute(proj_mma_kernel, cudaFuncAttributeMaxDynamicSharedMemorySize, PROJ_SMEM);

    convert_kernel<<<2432, 256>>>(x, Wt, Wp, Wa);                  // 1
    zero_logits_kernel<<<8, 1024>>>();                             // 2
    proj_mma_kernel<<<dim3(128, 3), 128, PROJ_SMEM>>>(bt, bp, ba); // 3
    fat_kernel<<<768, 128, FLASH_SMEM>>>(x, Wd);                   // 4  flash+gate overlapped
    gate_softmax<<<8, 1024>>>(bd);                                 // 5
    epilogue_kernel<<<256, 256>>>(x, Wm, out);                     // 6
}

// round 16
// speedup vs baseline: 1.6424x; 1.2014x over previous
#include <cuda_runtime.h>
#include <cuda_bf16.h>
#include <cstdint>

#define NTOK 8192
#define DIM  128
#define CIN  256
#define HWD  1024
#define LOG2E 1.4426950408889634f
#define NSPLIT 2
#define KVTILES 64
#define GATE_CHUNKS 512      // 512 chunks x 512 k-rows

// ---------------- device workspaces ----------------
__device__ __align__(256) __nv_bfloat16 g_xb[NTOK * CIN];
__device__ __align__(256) __nv_bfloat16 g_Wb[3 * DIM * CIN];   // W^T bf16 [sel][n][k]
__device__ __align__(256) __nv_bfloat16 g_Q[NTOK * DIM];
__device__ __align__(256) __nv_bfloat16 g_K[NTOK * DIM];
__device__ __align__(256) __nv_bfloat16 g_V[NTOK * DIM];
__device__ __align__(256) float g_Opart[NSPLIT * NTOK * DIM];
__device__ float g_m[NSPLIT * NTOK];
__device__ float g_l[NSPLIT * NTOK];
__device__ float g_logits[8 * HWD];
__device__ float g_sp[8 * HWD];

// ---------------- PTX helpers ----------------
__device__ __forceinline__ uint32_t smem_u32(const void* p) {
    return (uint32_t)__cvta_generic_to_shared(p);
}
__device__ __forceinline__ void ldsm_x4(uint32_t& r0, uint32_t& r1, uint32_t& r2, uint32_t& r3, uint32_t a) {
    asm volatile("ldmatrix.sync.aligned.m8n8.x4.shared.b16 {%0,%1,%2,%3},[%4];"
                 : "=r"(r0), "=r"(r1), "=r"(r2), "=r"(r3) : "r"(a));
}
__device__ __forceinline__ void ldsm_x4_t(uint32_t& r0, uint32_t& r1, uint32_t& r2, uint32_t& r3, uint32_t a) {
    asm volatile("ldmatrix.sync.aligned.m8n8.x4.trans.shared.b16 {%0,%1,%2,%3},[%4];"
                 : "=r"(r0), "=r"(r1), "=r"(r2), "=r"(r3) : "r"(a));
}
__device__ __forceinline__ void mma16816(float c[4], const uint32_t a[4], uint32_t b0, uint32_t b1) {
    asm volatile("mma.sync.aligned.m16n8k16.row.col.f32.bf16.bf16.f32 "
                 "{%0,%1,%2,%3},{%4,%5,%6,%7},{%8,%9},{%0,%1,%2,%3};"
                 : "+f"(c[0]), "+f"(c[1]), "+f"(c[2]), "+f"(c[3])
                 : "r"(a[0]), "r"(a[1]), "r"(a[2]), "r"(a[3]), "r"(b0), "r"(b1));
}
__device__ __forceinline__ float ex2f(float x) {
    float r; asm("ex2.approx.f32 %0,%1;" : "=f"(r) : "f"(x)); return r;
}
__device__ __forceinline__ uint32_t packbf(float lo, float hi) {
    uint32_t r; asm("cvt.rn.bf16x2.f32 %0,%1,%2;" : "=r"(r) : "f"(hi), "f"(lo)); return r;
}
__device__ __forceinline__ void ffma2(unsigned long long& acc, unsigned long long a, unsigned long long b) {
    asm("fma.rn.f32x2 %0, %1, %2, %0;" : "+l"(acc) : "l"(a), "l"(b));
}
__device__ __forceinline__ unsigned long long bcast2(float v) {
    unsigned long long r; asm("mov.b64 %0, {%1, %1};" : "=l"(r) : "f"(v)); return r;
}
__device__ __forceinline__ float2 unpack2(unsigned long long v) {
    float2 r; asm("mov.b64 {%0, %1}, %2;" : "=f"(r.x), "=f"(r.y) : "l"(v)); return r;
}

// ==================== convert: x -> bf16, W{t,p,a} -> bf16 transposed ====================
__global__ void convert_kernel(const float* __restrict__ x,
                               const float* __restrict__ Wt,
                               const float* __restrict__ Wp,
                               const float* __restrict__ Wa) {
    const int bx = blockIdx.x, tid = threadIdx.x;
    if (bx < 2048) {
        int gid = bx * 256 + tid;
        float4 v = *(const float4*)(x + (size_t)gid * 4);
        uint2 p;
        p.x = packbf(v.x, v.y);
        p.y = packbf(v.z, v.w);
        *(uint2*)(g_xb + (size_t)gid * 4) = p;
    } else {
        int i = (bx - 2048) * 256 + tid;
        int sel = i >> 15;
        int k = i & 255;
        int n = (i >> 8) & 127;
        const float* W = (sel == 0) ? Wt : (sel == 1) ? Wp : Wa;
        g_Wb[sel * 32768 + n * 256 + k] = __float2bfloat16(W[k * 128 + n]);
    }
}

// ==================== proj via tensor cores ====================
#define PROWP 264
#define PROJ_SMEM ((64 + 128) * PROWP * 2)

__global__ void __launch_bounds__(128) proj_mma_kernel(const float* __restrict__ bt,
                                                       const float* __restrict__ bp,
                                                       const float* __restrict__ ba) {
    extern __shared__ __align__(16) __nv_bfloat16 psh[];
    __nv_bfloat16* sA = psh;
    __nv_bfloat16* sB = psh + 64 * PROWP;
    __shared__ float sbias[128];
    const int sel = blockIdx.y;
    const float* bias = (sel == 0) ? bt : (sel == 1) ? bp : ba;
    __nv_bfloat16* dst = (sel == 0) ? g_Q : (sel == 1) ? g_K : g_V;
    const __nv_bfloat16* A = g_xb + (size_t)blockIdx.x * 64 * CIN;
    const __nv_bfloat16* B = g_Wb + (size_t)sel * DIM * CIN;
    const int tid = threadIdx.x, lane = tid & 31, warp = tid >> 5;

    sbias[tid] = bias[tid];

#pragma unroll
    for (int p = 0; p < 16; ++p) {
        int idx = p * 128 + tid;
        int row = idx >> 5, cc = idx & 31;
        uint32_t d = smem_u32(sA + row * PROWP + cc * 8);
        asm volatile("cp.async.cg.shared.global [%0],[%1],16;" :: "r"(d), "l"(A + row * CIN + cc * 8) : "memory");
    }
#pragma unroll
    for (int p = 0; p < 32; ++p) {
        int idx = p * 128 + tid;
        int row = idx >> 5, cc = idx & 31;
        uint32_t d = smem_u32(sB + row * PROWP + cc * 8);
        asm volatile("cp.async.cg.shared.global [%0],[%1],16;" :: "r"(d), "l"(B + row * CIN + cc * 8) : "memory");
    }
    asm volatile("cp.async.commit_group;" ::: "memory");
    asm volatile("cp.async.wait_group 0;" ::: "memory");
    __syncthreads();

    uint32_t af[16][4];
    {
        int arow = warp * 16 + (lane & 7) + ((lane & 8) ? 8 : 0);
        int acb = (lane & 16) ? 8 : 0;
#pragma unroll
        for (int kk = 0; kk < 16; ++kk)
            ldsm_x4(af[kk][0], af[kk][1], af[kk][2], af[kk][3],
                    smem_u32(sA + arow * PROWP + kk * 16 + acb));
    }
    float acc[16][4];
#pragma unroll
    for (int n = 0; n < 16; ++n) { acc[n][0] = acc[n][1] = acc[n][2] = acc[n][3] = 0.f; }

    const int brow = (lane & 7) + ((lane & 16) ? 8 : 0);
    const int bc8  = (lane & 8) ? 8 : 0;
#pragma unroll
    for (int kk = 0; kk < 16; ++kk) {
#pragma unroll
        for (int np = 0; np < 8; ++np) {
            uint32_t b0, b1, b2, b3;
            ldsm_x4(b0, b1, b2, b3, smem_u32(sB + (np * 16 + brow) * PROWP + kk * 16 + bc8));
            mma16816(acc[2 * np],     af[kk], b0, b1);
            mma16816(acc[2 * np + 1], af[kk], b2, b3);
        }
    }

    int r0 = blockIdx.x * 64 + warp * 16 + (lane >> 2);
    int c0 = 2 * (lane & 3);
#pragma unroll
    for (int n = 0; n < 16; ++n) {
        int c = n * 8 + c0;
        float b0v = sbias[c], b1v = sbias[c + 1];
        *(uint32_t*)&dst[(size_t)r0 * DIM + c]       = packbf(acc[n][0] + b0v, acc[n][1] + b1v);
        *(uint32_t*)&dst[(size_t)(r0 + 8) * DIM + c] = packbf(acc[n][2] + b0v, acc[n][3] + b1v);
    }
}

// ==================== gate body: software-pipelined (8 LDG.128 in flight) ====================
__device__ void gate_body(const float* __restrict__ x, const float* __restrict__ Wd,
                          int chunk, float* xs) {
    const int tid = threadIdx.x;
    const int k0 = chunk * 512;
    for (int i = tid; i < 4096; i += 128) {
        int kl = i & 511, b = i >> 9;
        xs[kl * 8 + b] = x[(size_t)b * 262144 + k0 + kl];
    }
    __syncthreads();

    unsigned long long acc[8][4];
#pragma unroll
    for (int b = 0; b < 8; ++b)
#pragma unroll
        for (int c = 0; c < 4; ++c) acc[b][c] = 0ull;

    const int cA = tid * 4, cB = 512 + tid * 4;

    // prefetch group 0 (4 k-rows x 2 LDG.128)
    longlong2 pw[4][2];
    {
        const float* wr = Wd + (size_t)k0 * 1024;
#pragma unroll
        for (int r = 0; r < 4; ++r) {
            pw[r][0] = __ldcs((const longlong2*)(wr + (size_t)r * 1024 + cA));
            pw[r][1] = __ldcs((const longlong2*)(wr + (size_t)r * 1024 + cB));
        }
    }

    for (int kl = 0; kl < 512; kl += 4) {
        longlong2 cur[4][2];
#pragma unroll
        for (int r = 0; r < 4; ++r) { cur[r][0] = pw[r][0]; cur[r][1] = pw[r][1]; }
        if (kl + 4 < 512) {
            const float* wr = Wd + (size_t)(k0 + kl + 4) * 1024;
#pragma unroll
            for (int r = 0; r < 4; ++r) {
                pw[r][0] = __ldcs((const longlong2*)(wr + (size_t)r * 1024 + cA));
                pw[r][1] = __ldcs((const longlong2*)(wr + (size_t)r * 1024 + cB));
            }
        }
#pragma unroll
        for (int r = 0; r < 4; ++r) {
            unsigned long long w0 = (unsigned long long)cur[r][0].x, w1 = (unsigned long long)cur[r][0].y;
            unsigned long long w2 = (unsigned long long)cur[r][1].x, w3 = (unsigned long long)cur[r][1].y;
            float4 xa = *(const float4*)&xs[(kl + r) * 8];
            float4 xb = *(const float4*)&xs[(kl + r) * 8 + 4];
            unsigned long long xp;
            xp = bcast2(xa.x); ffma2(acc[0][0], w0, xp); ffma2(acc[0][1], w1, xp); ffma2(acc[0][2], w2, xp); ffma2(acc[0][3], w3, xp);
            xp = bcast2(xa.y); ffma2(acc[1][0], w0, xp); ffma2(acc[1][1], w1, xp); ffma2(acc[1][2], w2, xp); ffma2(acc[1][3], w3, xp);
            xp = bcast2(xa.z); ffma2(acc[2][0], w0, xp); ffma2(acc[2][1], w1, xp); ffma2(acc[2][2], w2, xp); ffma2(acc[2][3], w3, xp);
            xp = bcast2(xa.w); ffma2(acc[3][0], w0, xp); ffma2(acc[3][1], w1, xp); ffma2(acc[3][2], w2, xp); ffma2(acc[3][3], w3, xp);
            xp = bcast2(xb.x); ffma2(acc[4][0], w0, xp); ffma2(acc[4][1], w1, xp); ffma2(acc[4][2], w2, xp); ffma2(acc[4][3], w3, xp);
            xp = bcast2(xb.y); ffma2(acc[5][0], w0, xp); ffma2(acc[5][1], w1, xp); ffma2(acc[5][2], w2, xp); ffma2(acc[5][3], w3, xp);
            xp = bcast2(xb.z); ffma2(acc[6][0], w0, xp); ffma2(acc[6][1], w1, xp); ffma2(acc[6][2], w2, xp); ffma2(acc[6][3], w3, xp);
            xp = bcast2(xb.w); ffma2(acc[7][0], w0, xp); ffma2(acc[7][1], w1, xp); ffma2(acc[7][2], w2, xp); ffma2(acc[7][3], w3, xp);
        }
    }
#pragma unroll
    for (int b = 0; b < 8; ++b) {
        float2 v0 = unpack2(acc[b][0]);
        float2 v1 = unpack2(acc[b][1]);
        float2 v2 = unpack2(acc[b][2]);
        float2 v3 = unpack2(acc[b][3]);
        float* p = g_logits + b * HWD;
        atomicAdd(p + cA + 0, v0.x); atomicAdd(p + cA + 1, v0.y);
        atomicAdd(p + cA + 2, v1.x); atomicAdd(p + cA + 3, v1.y);
        atomicAdd(p + cB + 0, v2.x); atomicAdd(p + cB + 1, v2.y);
        atomicAdd(p + cB + 2, v3.x); atomicAdd(p + cB + 3, v3.y);
    }
}

// ==================== fat kernel: flash (even bids < 512) + gate (others) ====================
#define ROWP 136
#define TILEB (64 * ROWP)
#define FLASH_SMEM (5 * TILEB * 2)

__device__ __forceinline__ void load_tile(__nv_bfloat16* dst, const __nv_bfloat16* src, int tid) {
#pragma unroll
    for (int it = 0; it < 8; ++it) {
        int c = tid + it * 128;
        int row = c >> 4, cc = c & 15;
        uint32_t d = smem_u32(dst + row * ROWP + cc * 8);
        const void* s = src + row * DIM + cc * 8;
        asm volatile("cp.async.cg.shared.global [%0],[%1],16;" :: "r"(d), "l"(s) : "memory");
    }
}

__global__ void __launch_bounds__(128, 2) fat_kernel(const float* __restrict__ x,
                                                     const float* __restrict__ Wd) {
    extern __shared__ __align__(16) __nv_bfloat16 sh[];
    const int bid = blockIdx.x;

    if (bid >= 512 || (bid & 1)) {
        int chunk = (bid >= 512) ? (256 + bid - 512) : (bid >> 1);
        gate_body(x, Wd, chunk, (float*)sh);
        return;
    }
    const int fidx = bid >> 1;                // 0..255
    const int q0 = (fidx >> 1) * 64;
    const int split = fidx & 1;

    __nv_bfloat16* sQ = sh;
    __nv_bfloat16* sK = sh + TILEB;
    __nv_bfloat16* sV = sh + 3 * TILEB;
    const int tid = threadIdx.x, lane = tid & 31, warp = tid >> 5;
    const __nv_bfloat16* Kbase = g_K + (size_t)split * KVTILES * 64 * DIM;
    const __nv_bfloat16* Vbase = g_V + (size_t)split * KVTILES * 64 * DIM;

    load_tile(sQ, g_Q + (size_t)q0 * DIM, tid);
    asm volatile("cp.async.commit_group;" ::: "memory");
    load_tile(sK, Kbase, tid);
    load_tile(sV, Vbase, tid);
    asm volatile("cp.async.commit_group;" ::: "memory");
    asm volatile("cp.async.wait_group 1;" ::: "memory");
    __syncthreads();

    uint32_t qf[8][4];
    {
        int row = warp * 16 + (lane & 7) + ((lane & 8) ? 8 : 0);
        int cb = (lane & 16) ? 8 : 0;
#pragma unroll
        for (int kk = 0; kk < 8; ++kk)
            ldsm_x4(qf[kk][0], qf[kk][1], qf[kk][2], qf[kk][3],
                    smem_u32(sQ + row * ROWP + kk * 16 + cb));
    }

    float oacc[16][4];
#pragma unroll
    for (int n = 0; n < 16; ++n) { oacc[n][0] = oacc[n][1] = oacc[n][2] = oacc[n][3] = 0.f; }
    float m0 = -1e30f, m1 = -1e30f, l0 = 0.f, l1 = 0.f;

    const int krow = (lane & 7) + ((lane & 16) ? 8 : 0);
    const int kc8  = (lane & 8) ? 8 : 0;
    const int vrow = (lane & 7) + ((lane & 8) ? 8 : 0);
    const int vc8  = (lane & 16) ? 8 : 0;

    for (int t = 0; t < KVTILES; ++t) {
        const int buf = t & 1;
        if (t < KVTILES - 1) {
            load_tile(sK + (1 - buf) * TILEB, Kbase + (size_t)(t + 1) * 64 * DIM, tid);
            load_tile(sV + (1 - buf) * TILEB, Vbase + (size_t)(t + 1) * 64 * DIM, tid);
        }
        asm volatile("cp.async.commit_group;" ::: "memory");
        asm volatile("cp.async.wait_group 1;" ::: "memory");
        __syncthreads();
        const __nv_bfloat16* kb = sK + buf * TILEB;
        const __nv_bfloat16* vb = sV + buf * TILEB;

        float sacc[8][4];
#pragma unroll
        for (int n = 0; n < 8; ++n) { sacc[n][0] = sacc[n][1] = sacc[n][2] = sacc[n][3] = 0.f; }
#pragma unroll
        for (int kk = 0; kk < 8; ++kk) {
#pragma unroll
            for (int np = 0; np < 4; ++np) {
                uint32_t b0, b1, b2, b3;
                ldsm_x4(b0, b1, b2, b3, smem_u32(kb + (np * 16 + krow) * ROWP + kk * 16 + kc8));
                mma16816(sacc[2 * np],     qf[kk], b0, b1);
                mma16816(sacc[2 * np + 1], qf[kk], b2, b3);
            }
        }

        float mx0 = -1e30f, mx1 = -1e30f;
#pragma unroll
        for (int n = 0; n < 8; ++n) {
            mx0 = fmaxf(mx0, fmaxf(sacc[n][0], sacc[n][1]));
            mx1 = fmaxf(mx1, fmaxf(sacc[n][2], sacc[n][3]));
        }
        mx0 = fmaxf(mx0, __shfl_xor_sync(0xffffffffu, mx0, 1));
        mx0 = fmaxf(mx0, __shfl_xor_sync(0xffffffffu, mx0, 2));
        mx1 = fmaxf(mx1, __shfl_xor_sync(0xffffffffu, mx1, 1));
        mx1 = fmaxf(mx1, __shfl_xor_sync(0xffffffffu, mx1, 2));
        float mn0 = fmaxf(m0, mx0), mn1 = fmaxf(m1, mx1);
        float sc0 = ex2f((m0 - mn0) * LOG2E), sc1 = ex2f((m1 - mn1) * LOG2E);
        float rs0 = 0.f, rs1 = 0.f;
#pragma unroll
        for (int n = 0; n < 8; ++n) {
            sacc[n][0] = ex2f((sacc[n][0] - mn0) * LOG2E);
            sacc[n][1] = ex2f((sacc[n][1] - mn0) * LOG2E);
            sacc[n][2] = ex2f((sacc[n][2] - mn1) * LOG2E);
            sacc[n][3] = ex2f((sacc[n][3] - mn1) * LOG2E);
            rs0 += sacc[n][0] + sacc[n][1];
            rs1 += sacc[n][2] + sacc[n][3];
        }
        rs0 += __shfl_xor_sync(0xffffffffu, rs0, 1);
        rs0 += __shfl_xor_sync(0xffffffffu, rs0, 2);
        rs1 += __shfl_xor_sync(0xffffffffu, rs1, 1);
        rs1 += __shfl_xor_sync(0xffffffffu, rs1, 2);
        l0 = l0 * sc0 + rs0; l1 = l1 * sc1 + rs1;
        m0 = mn0; m1 = mn1;
#pragma unroll
        for (int n = 0; n < 16; ++n) {
            oacc[n][0] *= sc0; oacc[n][1] *= sc0;
            oacc[n][2] *= sc1; oacc[n][3] *= sc1;
        }

        uint32_t pf[4][4];
#pragma unroll
        for (int i = 0; i < 4; ++i) {
            pf[i][0] = packbf(sacc[2 * i][0],     sacc[2 * i][1]);
            pf[i][1] = packbf(sacc[2 * i][2],     sacc[2 * i][3]);
            pf[i][2] = packbf(sacc[2 * i + 1][0], sacc[2 * i + 1][1]);
            pf[i][3] = packbf(sacc[2 * i + 1][2], sacc[2 * i + 1][3]);
        }

#pragma unroll
        for (int i = 0; i < 4; ++i) {
#pragma unroll
            for (int np = 0; np < 8; ++np) {
                uint32_t b0, b1, b2, b3;
                ldsm_x4_t(b0, b1, b2, b3, smem_u32(vb + (i * 16 + vrow) * ROWP + np * 16 + vc8));
                mma16816(oacc[2 * np],     pf[i], b0, b1);
                mma16816(oacc[2 * np + 1], pf[i], b2, b3);
            }
        }
        __syncthreads();
    }

    float* Op = g_Opart + (size_t)split * NTOK * DIM;
    int row0 = q0 + warp * 16 + (lane >> 2);
    int c0 = 2 * (lane & 3);
#pragma unroll
    for (int n = 0; n < 16; ++n) {
        int c = n * 8 + c0;
        *(float2*)&Op[(size_t)row0 * DIM + c]       = make_float2(oacc[n][0], oacc[n][1]);
        *(float2*)&Op[(size_t)(row0 + 8) * DIM + c] = make_float2(oacc[n][2], oacc[n][3]);
    }
    if ((lane & 3) == 0) {
        g_m[split * NTOK + row0] = m0;     g_l[split * NTOK + row0] = l0;
        g_m[split * NTOK + row0 + 8] = m1; g_l[split * NTOK + row0 + 8] = l1;
    }
}

// ==================== small kernels ====================
__global__ void zero_logits_kernel() {
    g_logits[blockIdx.x * 1024 + threadIdx.x] = 0.f;
}

__global__ void gate_softmax(const float* __restrict__ bd) {
    __shared__ float red[32];
    __shared__ float bc;
    const int b = blockIdx.x, j = threadIdx.x;
    const int lane = j & 31, w = j >> 5;
    float v = g_logits[b * HWD + j] + bd[j];
    float m = v;
#pragma unroll
    for (int o = 16; o; o >>= 1) m = fmaxf(m, __shfl_xor_sync(0xffffffffu, m, o));
    if (lane == 0) red[w] = m;
    __syncthreads();
    if (j < 32) {
        float t = red[j];
#pragma unroll
        for (int o = 16; o; o >>= 1) t = fmaxf(t, __shfl_xor_sync(0xffffffffu, t, o));
        if (j == 0) bc = t;
    }
    __syncthreads();
    float e = expf(v - bc);
    float s = e;
#pragma unroll
    for (int o = 16; o; o >>= 1) s += __shfl_xor_sync(0xffffffffu, s, o);
    if (lane == 0) red[w] = s;
    __syncthreads();
    if (j < 32) {
        float t = red[j];
#pragma unroll
        for (int o = 16; o; o >>= 1) t += __shfl_xor_sync(0xffffffffu, t, o);
        if (j == 0) bc = t;
    }
    __syncthreads();
    g_sp[b * HWD + j] = e / bc;
}

// ==================== epilogue ====================
__global__ void epilogue_kernel(const float* __restrict__ x, const float* __restrict__ Wm,
                                float* __restrict__ out) {
    __shared__ float4 sO[32 * 32];
    __shared__ float ssp[32], sw0[32], sw1[32], sinv[32];
    const int tid = threadIdx.x;
    const int t0 = blockIdx.x * 32;
    if (tid < 32) {
        int r = t0 + tid;
        float m0 = g_m[r], m1 = g_m[NTOK + r];
        float l0 = g_l[r], l1 = g_l[NTOK + r];
        float mm = fmaxf(m0, m1);
        float w0 = ex2f((m0 - mm) * LOG2E), w1 = ex2f((m1 - mm) * LOG2E);
        sw0[tid] = w0; sw1[tid] = w1;
        sinv[tid] = 1.f / (l0 * w0 + l1 * w1);
        ssp[tid] = g_sp[r];
    }
    __syncthreads();
    const float4* o0 = (const float4*)(g_Opart + (size_t)t0 * DIM);
    const float4* o1 = (const float4*)(g_Opart + (size_t)NTOK * DIM + (size_t)t0 * DIM);
    for (int i = tid; i < 1024; i += 256) {
        int t = i >> 5;
        float w0 = sw0[t] * sinv[t], w1 = sw1[t] * sinv[t];
        float4 a = o0[i], b = o1[i];
        sO[i] = make_float4(a.x * w0 + b.x * w1, a.y * w0 + b.y * w1,
                            a.z * w0 + b.z * w1, a.w * w0 + b.w * w1);
    }
    __syncthreads();
    const int j = tid;
    float acc[32];
#pragma unroll
    for (int t = 0; t < 32; ++t) acc[t] = 0.f;
    for (int k4 = 0; k4 < 32; ++k4) {
        float w0 = Wm[(k4 * 4 + 0) * CIN + j];
        float w1 = Wm[(k4 * 4 + 1) * CIN + j];
        float w2 = Wm[(k4 * 4 + 2) * CIN + j];
        float w3 = Wm[(k4 * 4 + 3) * CIN + j];
#pragma unroll
        for (int t = 0; t < 32; ++t) {
            float4 v = sO[t * 32 + k4];
            acc[t] = fmaf(v.x, w0, acc[t]);
            acc[t] = fmaf(v.y, w1, acc[t]);
            acc[t] = fmaf(v.z, w2, acc[t]);
            acc[t] = fmaf(v.w, w3, acc[t]);
        }
    }
#pragma unroll
    for (int t = 0; t < 32; ++t)
        out[(size_t)(t0 + t) * CIN + j] = acc[t] * ssp[t] + x[(size_t)(t0 + t) * CIN + j];
}

// ==================== launcher ====================
extern "C" void kernel_launch(void* const* d_in, const int* in_sizes, int n_in,
                              void* d_out, int out_size) {
    const float* x  = (const float*)d_in[0];
    const float* Wt = (const float*)d_in[1];
    const float* bt = (const float*)d_in[2];
    const float* Wp = (const float*)d_in[3];
    const float* bp = (const float*)d_in[4];
    const float* Wa = (const float*)d_in[5];
    const float* ba = (const float*)d_in[6];
    const float* Wm = (const float*)d_in[7];
    const float* Wd = (const float*)d_in[8];
    const float* bd = (const float*)d_in[9];
    float* out = (float*)d_out;

    cudaFuncSetAttribute(fat_kernel, cudaFuncAttributeMaxDynamicSharedMemorySize, FLASH_SMEM);
    cudaFuncSetAttribute(proj_mma_kernel, cudaFuncAttributeMaxDynamicSharedMemorySize, PROJ_SMEM);

    convert_kernel<<<2432, 256>>>(x, Wt, Wp, Wa);                  // 1
    zero_logits_kernel<<<8, 1024>>>();                             // 2
    proj_mma_kernel<<<dim3(128, 3), 128, PROJ_SMEM>>>(bt, bp, ba); // 3
    fat_kernel<<<768, 128, FLASH_SMEM>>>(x, Wd);                   // 4  flash+gate overlapped
    gate_softmax<<<8, 1024>>>(bd);                                 // 5
    epilogue_kernel<<<256, 256>>>(x, Wm, out);                     // 6
}